// round 14
// baseline (speedup 1.0000x reference)
#include <cuda_runtime.h>
#include <cuda_fp16.h>
#include <math.h>
#include <stdint.h>

// Problem constants
#define B_    8
#define LQ    512
#define LKV   2048
#define QDIM  768
#define KVDIM 768
#define HID   1024
#define NH    16
#define DH    64
#define KVW   2048    // merged K|V projection row width

// ---------------------------------------------------------------------------
// Scratch (device globals)
// ---------------------------------------------------------------------------
__device__ __half g_Qp[(size_t)B_ * LQ * HID];     // projected Q (fp16)
__device__ __half g_KVp[(size_t)B_ * LKV * KVW];   // projected [K|V] (fp16)
__device__ __half g_Oh[(size_t)B_ * LQ * HID];     // attention out (fp16)
__device__ float  g_bias[B_ * LKV];                // mask bias (pre-scaled by log2e)
__device__ float  g_bkv[KVW];                      // [bk|bv] concatenated
__device__ int    g_mask_kind;
// fp16 prep buffers
__device__ __half g_Qh[(size_t)B_ * LQ * QDIM];    // query fp16 [M][K]
__device__ __half g_KVh[(size_t)B_ * LKV * KVDIM]; // key_value fp16 [M][K]
__device__ __half g_WqT[QDIM * HID];               // Wq^T fp16 [N][K]
__device__ __half g_WkvT[(size_t)KVW * KVDIM];     // [Wk^T | Wv^T] fp16 [2048][768]
__device__ __half g_WoT[HID * HID];

// ---------------------------------------------------------------------------
// Helpers
// ---------------------------------------------------------------------------
__device__ __forceinline__ void mma_f16(float d[4], const uint32_t a[4],
                                        uint32_t b0, uint32_t b1) {
    asm volatile(
        "mma.sync.aligned.m16n8k16.row.col.f32.f16.f16.f32 "
        "{%0,%1,%2,%3}, {%4,%5,%6,%7}, {%8,%9}, {%0,%1,%2,%3};\n"
        : "+f"(d[0]), "+f"(d[1]), "+f"(d[2]), "+f"(d[3])
        : "r"(a[0]), "r"(a[1]), "r"(a[2]), "r"(a[3]), "r"(b0), "r"(b1));
}

#define LDSM_X4(r, addr)                                                      \
    asm volatile("ldmatrix.sync.aligned.m8n8.x4.shared.b16 {%0,%1,%2,%3}, [%4];" \
                 : "=r"((r)[0]), "=r"((r)[1]), "=r"((r)[2]), "=r"((r)[3])     \
                 : "r"(addr))

#define LDSM_X4_T(r, addr)                                                    \
    asm volatile("ldmatrix.sync.aligned.m8n8.x4.trans.shared.b16 {%0,%1,%2,%3}, [%4];" \
                 : "=r"((r)[0]), "=r"((r)[1]), "=r"((r)[2]), "=r"((r)[3])     \
                 : "r"(addr))

__device__ __forceinline__ void cp16(uint32_t dst_smem, const void* src) {
    asm volatile("cp.async.cg.shared.global [%0], [%1], 16;\n"
                 :: "r"(dst_smem), "l"(src));
}

__device__ __forceinline__ uint32_t smem_u32(const void* p) {
    uint32_t a;
    asm("{ .reg .u64 t; cvta.to.shared.u64 t, %1; cvt.u32.u64 %0, t; }"
        : "=r"(a) : "l"(p));
    return a;
}

__device__ __forceinline__ uint32_t ph2(float lo, float hi) {
    __half2 h = __floats2half2_rn(lo, hi);
    return *reinterpret_cast<uint32_t*>(&h);
}

// ---------------------------------------------------------------------------
// Prep kernels
// ---------------------------------------------------------------------------
__global__ void to_half(const float* __restrict__ s, __half* __restrict__ d,
                        int n4) {
    for (int i = blockIdx.x * blockDim.x + threadIdx.x; i < n4;
         i += gridDim.x * blockDim.x) {
        float4 v = ((const float4*)s)[i];
        ((__half2*)d)[i * 2]     = __floats2half2_rn(v.x, v.y);
        ((__half2*)d)[i * 2 + 1] = __floats2half2_rn(v.z, v.w);
    }
}

// W[K][N] fp32 -> WT[N][K] fp16. block (32,8), grid (N/32, K/32).
__global__ void transpose_half(const float* __restrict__ s,
                               __half* __restrict__ d, int K, int N) {
    __shared__ float t[32][33];
    int n0 = blockIdx.x * 32, k0 = blockIdx.y * 32;
    int tx = threadIdx.x, ty = threadIdx.y;
    #pragma unroll
    for (int i = 0; i < 32; i += 8)
        t[ty + i][tx] = s[(size_t)(k0 + ty + i) * N + n0 + tx];
    __syncthreads();
    #pragma unroll
    for (int i = 0; i < 32; i += 8)
        d[(size_t)(n0 + ty + i) * K + k0 + tx] = __float2half(t[tx][ty + i]);
}

__global__ void concat_bias(const float* __restrict__ a,
                            const float* __restrict__ b) {
    int i = blockIdx.x * blockDim.x + threadIdx.x;
    if (i < HID) { g_bkv[i] = a[i]; g_bkv[HID + i] = b[i]; }
}

// ---------------------------------------------------------------------------
// Mask dtype classification + bias build (bias pre-scaled by log2(e))
// ---------------------------------------------------------------------------
__global__ void detect_mask_kind_kernel(const unsigned int* __restrict__ w) {
    __shared__ int bad_f32, bad_i32;
    if (threadIdx.x == 0) { bad_f32 = 0; bad_i32 = 0; }
    __syncthreads();
    int lf = 0, li = 0;
    for (int i = threadIdx.x; i < (B_ * LKV) / 4; i += blockDim.x) {
        unsigned int x = w[i];
        if (!(x == 0u || x == 0x3f800000u)) lf = 1;
        if (!(x == 0u || x == 1u))          li = 1;
    }
    if (lf) bad_f32 = 1;
    if (li) bad_i32 = 1;
    __syncthreads();
    if (threadIdx.x == 0)
        g_mask_kind = (!bad_f32) ? 0 : ((!bad_i32) ? 1 : 2);
}

__global__ void build_bias_kernel(const void* __restrict__ mp) {
    int i = blockIdx.x * blockDim.x + threadIdx.x;
    if (i >= B_ * LKV) return;
    int k = g_mask_kind;
    bool on;
    if (k == 0)      on = (((const float*)mp)[i] != 0.0f);
    else if (k == 1) on = (((const int*)mp)[i] != 0);
    else             on = (((const unsigned char*)mp)[i] != 0);
    g_bias[i] = on ? 0.0f : -1.4426950e30f;   // -1e30 * log2(e)
}

// ---------------------------------------------------------------------------
// FP16 tensor-core GEMM:  C[M,N] = A[M,K] @ BT[N,K]^T + bias[N]  (f32 accum)
// Block 128x128, 256 threads (8 warps, 2Mx4N), warp 64x32. K-tile 32 halves.
// 2-stage cp.async, single sync/iter; ldmatrix frags, 80 B stride (64B rows).
// Exactly one of Cf / Ch is non-null: fp32 or fp16 output.
// ---------------------------------------------------------------------------
#define GSTAGE 10240   // 128 rows * 80 B

#define LOAD_F16(st, k0)                                                      \
    do {                                                                      \
        _Pragma("unroll")                                                     \
        for (int i = 0; i < 2; i++) {                                         \
            int idx = tid + i * 256;                                          \
            int r = idx >> 2, c = idx & 3;                                    \
            cp16(saA + (st) * GSTAGE + r * 80 + c * 16,                       \
                 A + (size_t)(bym + r) * K + (k0) + c * 8);                   \
            cp16(saB + (st) * GSTAGE + r * 80 + c * 16,                       \
                 BT + (size_t)(bxn + r) * K + (k0) + c * 8);                  \
        }                                                                     \
        asm volatile("cp.async.commit_group;\n" ::: "memory");                \
    } while (0)

__global__ __launch_bounds__(256, 2) void gemm_f16(
    const __half* __restrict__ A, const __half* __restrict__ BT,
    const float* __restrict__ bias, float* __restrict__ Cf,
    __half* __restrict__ Ch, int M, int N, int K)
{
    __shared__ __align__(16) __half As[2][128][40];
    __shared__ __align__(16) __half Bs[2][128][40];

    const int tid  = threadIdx.x;
    const int lane = tid & 31;
    const int wid  = tid >> 5;
    const int g    = lane >> 2;
    const int tig  = lane & 3;
    const int wm   = (wid >> 2) * 64;
    const int wn   = (wid & 3) * 32;
    const int bym  = blockIdx.y * 128;
    const int bxn  = blockIdx.x * 128;

    const uint32_t saA = smem_u32(&As[0][0][0]);
    const uint32_t saB = smem_u32(&Bs[0][0][0]);

    const int lr  = lane & 7;
    const int seg = lane >> 3;
    const uint32_t aOff = (uint32_t)(wm + lr + (seg & 1) * 8) * 80
                        + ((seg >> 1) & 1) * 16;
    const uint32_t bOff = (uint32_t)(wn + lr + ((seg >> 1) & 1) * 8) * 80
                        + (seg & 1) * 16;

    float acc[4][4][4];
    #pragma unroll
    for (int mi = 0; mi < 4; mi++)
        #pragma unroll
        for (int nj = 0; nj < 4; nj++)
            #pragma unroll
            for (int f = 0; f < 4; f++) acc[mi][nj][f] = 0.0f;

    const int T = K >> 5;
    LOAD_F16(0, 0);

    for (int t = 0; t < T; t++) {
        const int s = t & 1;
        asm volatile("cp.async.wait_group 0;\n" ::: "memory");
        __syncthreads();
        if (t + 1 < T) LOAD_F16(s ^ 1, (t + 1) << 5);

        const uint32_t aS = saA + s * GSTAGE + aOff;
        const uint32_t bS = saB + s * GSTAGE + bOff;
        #pragma unroll
        for (int ks = 0; ks < 2; ks++) {
            const uint32_t kb = ks * 32;
            uint32_t af[4][4], bf[2][4];
            #pragma unroll
            for (int mi = 0; mi < 4; mi++)
                LDSM_X4(af[mi], aS + mi * (16 * 80) + kb);
            #pragma unroll
            for (int p = 0; p < 2; p++)
                LDSM_X4(bf[p], bS + p * (16 * 80) + kb);
            #pragma unroll
            for (int mi = 0; mi < 4; mi++)
                #pragma unroll
                for (int nj = 0; nj < 4; nj++)
                    mma_f16(acc[mi][nj], af[mi],
                            bf[nj >> 1][(nj & 1) * 2],
                            bf[nj >> 1][(nj & 1) * 2 + 1]);
        }
    }

    #pragma unroll
    for (int mi = 0; mi < 4; mi++) {
        int row = bym + wm + mi * 16 + g;
        #pragma unroll
        for (int nj = 0; nj < 4; nj++) {
            int col = bxn + wn + nj * 8 + 2 * tig;
            float b0 = bias[col], b1 = bias[col + 1];
            float v00 = acc[mi][nj][0] + b0, v01 = acc[mi][nj][1] + b1;
            float v10 = acc[mi][nj][2] + b0, v11 = acc[mi][nj][3] + b1;
            if (Ch) {
                *(__half2*)&Ch[(size_t)row * N + col] =
                    __floats2half2_rn(v00, v01);
                *(__half2*)&Ch[(size_t)(row + 8) * N + col] =
                    __floats2half2_rn(v10, v11);
            } else {
                *(float2*)&Cf[(size_t)row * N + col] = make_float2(v00, v01);
                *(float2*)&Cf[(size_t)(row + 8) * N + col] =
                    make_float2(v10, v11);
            }
        }
    }
}

// ---------------------------------------------------------------------------
// Fused flash attention, fp16 mma (m16n8k16), register-resident P.
// grid = (LQ/128, B*NH), 256 threads (8 warps), warp owns 16 q-rows.
// K/V from the merged [K|V] projection (row width KVW=2048).
// 64-row KV tiles (128 B rows), smem stride 144 B (conflict-free ldmatrix).
// 2-stage cp.async pipeline, one __syncthreads per tile.
// Softmax in exp2 domain (scale and mask bias pre-folded with log2(e)).
// ---------------------------------------------------------------------------
#define ASTR 144              // bytes per KV row in smem
#define ASTG (64 * ASTR)      // 9216 B per stage per tensor
#define SC2  0.18033688f      // 0.125 * log2(e)

#define LOAD_KV(st, j0)                                                       \
    do {                                                                      \
        _Pragma("unroll")                                                     \
        for (int i = 0; i < 2; i++) {                                         \
            int idx = tid + i * 256;                                          \
            int r = idx >> 3, c = idx & 7;                                    \
            cp16(ks0 + (st) * ASTG + r * ASTR + c * 16,                       \
                 Kg + (size_t)((j0) + r) * KVW + c * 8);                      \
            cp16(vs0 + (st) * ASTG + r * ASTR + c * 16,                       \
                 Vg + (size_t)((j0) + r) * KVW + c * 8);                      \
        }                                                                     \
        asm volatile("cp.async.commit_group;\n" ::: "memory");                \
    } while (0)

__global__ __launch_bounds__(256) void attn_f16() {
    __shared__ __align__(16) __half Ks[2][64][ASTR / 2];
    __shared__ __align__(16) __half Vs[2][64][ASTR / 2];

    const int tid  = threadIdx.x;
    const int lane = tid & 31;
    const int w    = tid >> 5;
    const int g    = lane >> 2;
    const int tig  = lane & 3;
    const int lr   = lane & 7;
    const int seg  = lane >> 3;
    const int bh   = blockIdx.y;
    const int b    = bh >> 4;
    const int h    = bh & 15;
    const int q0   = blockIdx.x * 128;
    const int row0 = w * 16 + g;

    const __half* Qg = g_Qp + ((size_t)(b * LQ + q0)) * HID + h * DH;
    const __half* Kg = g_KVp + ((size_t)b * LKV) * KVW + h * DH;
    const __half* Vg = Kg + HID;   // V half of the merged row
    const float*  bg = g_bias + b * LKV;

    const uint32_t ks0 = smem_u32(&Ks[0][0][0]);
    const uint32_t vs0 = smem_u32(&Vs[0][0][0]);

    const uint32_t kOff = (uint32_t)(lr + ((seg >> 1) & 1) * 8) * ASTR
                        + (seg & 1) * 16;
    const uint32_t vOff = (uint32_t)(lr + (seg & 1) * 8) * ASTR
                        + ((seg >> 1) & 1) * 16;

    // ---- Q fragments from gmem fp16 (4 k-steps over d=64) ----
    uint32_t qf[4][4];
    {
        const __half* q0p = Qg + (size_t)row0 * HID;
        const __half* q8p = Qg + (size_t)(row0 + 8) * HID;
        #pragma unroll
        for (int kk = 0; kk < 4; kk++) {
            int col = kk * 16 + 2 * tig;
            qf[kk][0] = *(const uint32_t*)(q0p + col);
            qf[kk][1] = *(const uint32_t*)(q8p + col);
            qf[kk][2] = *(const uint32_t*)(q0p + col + 8);
            qf[kk][3] = *(const uint32_t*)(q8p + col + 8);
        }
    }

    float of[8][4];
    #pragma unroll
    for (int nj = 0; nj < 8; nj++)
        #pragma unroll
        for (int f = 0; f < 4; f++) of[nj][f] = 0.0f;
    float m0 = -1.0e30f, m1 = -1.0e30f, l0 = 0.0f, l1 = 0.0f;

    LOAD_KV(0, 0);

    for (int t = 0; t < LKV / 64; t++) {
        const int s  = t & 1;
        const int j0 = t * 64;
        asm volatile("cp.async.wait_group 0;\n" ::: "memory");
        __syncthreads();
        if (t + 1 < LKV / 64) LOAD_KV(s ^ 1, j0 + 64);

        const uint32_t kS = ks0 + s * ASTG;
        const uint32_t vS = vs0 + s * ASTG;

        // ---- S = Q K^T ----
        float sv[8][4];
        #pragma unroll
        for (int nj = 0; nj < 8; nj++)
            #pragma unroll
            for (int f = 0; f < 4; f++) sv[nj][f] = 0.0f;
        #pragma unroll
        for (int kk = 0; kk < 4; kk++) {
            #pragma unroll
            for (int p = 0; p < 4; p++) {
                uint32_t bf[4];
                LDSM_X4(bf, kS + kOff + p * (16 * ASTR) + kk * 32);
                mma_f16(sv[2 * p],     qf[kk], bf[0], bf[1]);
                mma_f16(sv[2 * p + 1], qf[kk], bf[2], bf[3]);
            }
        }

        // ---- scale + bias (exp2 domain), online softmax in registers ----
        float mx0 = -1.0e30f, mx1 = -1.0e30f;
        #pragma unroll
        for (int nj = 0; nj < 8; nj++) {
            float2 bb = *(const float2*)&bg[j0 + nj * 8 + 2 * tig];
            sv[nj][0] = sv[nj][0] * SC2 + bb.x;
            sv[nj][1] = sv[nj][1] * SC2 + bb.y;
            sv[nj][2] = sv[nj][2] * SC2 + bb.x;
            sv[nj][3] = sv[nj][3] * SC2 + bb.y;
            mx0 = fmaxf(mx0, fmaxf(sv[nj][0], sv[nj][1]));
            mx1 = fmaxf(mx1, fmaxf(sv[nj][2], sv[nj][3]));
        }
        mx0 = fmaxf(mx0, __shfl_xor_sync(0xffffffffu, mx0, 1));
        mx0 = fmaxf(mx0, __shfl_xor_sync(0xffffffffu, mx0, 2));
        mx1 = fmaxf(mx1, __shfl_xor_sync(0xffffffffu, mx1, 1));
        mx1 = fmaxf(mx1, __shfl_xor_sync(0xffffffffu, mx1, 2));
        float mn0 = fmaxf(m0, mx0), mn1 = fmaxf(m1, mx1);
        float c0 = exp2f(m0 - mn0), c1 = exp2f(m1 - mn1);
        m0 = mn0; m1 = mn1;

        float sum0 = 0.0f, sum1 = 0.0f;
        #pragma unroll
        for (int nj = 0; nj < 8; nj++) {
            sv[nj][0] = exp2f(sv[nj][0] - m0);
            sv[nj][1] = exp2f(sv[nj][1] - m0);
            sv[nj][2] = exp2f(sv[nj][2] - m1);
            sv[nj][3] = exp2f(sv[nj][3] - m1);
            sum0 += sv[nj][0] + sv[nj][1];
            sum1 += sv[nj][2] + sv[nj][3];
        }
        sum0 += __shfl_xor_sync(0xffffffffu, sum0, 1);
        sum0 += __shfl_xor_sync(0xffffffffu, sum0, 2);
        sum1 += __shfl_xor_sync(0xffffffffu, sum1, 1);
        sum1 += __shfl_xor_sync(0xffffffffu, sum1, 2);
        l0 = l0 * c0 + sum0;
        l1 = l1 * c1 + sum1;

        // ---- rescale O accumulators ----
        #pragma unroll
        for (int nj = 0; nj < 8; nj++) {
            of[nj][0] *= c0; of[nj][1] *= c0;
            of[nj][2] *= c1; of[nj][3] *= c1;
        }

        // ---- O += P V (register-packed P; V via trans ldmatrix) ----
        #pragma unroll
        for (int kk2 = 0; kk2 < 4; kk2++) {
            uint32_t pf[4];
            pf[0] = ph2(sv[2 * kk2][0],     sv[2 * kk2][1]);
            pf[1] = ph2(sv[2 * kk2][2],     sv[2 * kk2][3]);
            pf[2] = ph2(sv[2 * kk2 + 1][0], sv[2 * kk2 + 1][1]);
            pf[3] = ph2(sv[2 * kk2 + 1][2], sv[2 * kk2 + 1][3]);
            #pragma unroll
            for (int p2 = 0; p2 < 4; p2++) {
                uint32_t bf[4];
                LDSM_X4_T(bf, vS + vOff + kk2 * (16 * ASTR) + p2 * 32);
                mma_f16(of[2 * p2],     pf, bf[0], bf[1]);
                mma_f16(of[2 * p2 + 1], pf, bf[2], bf[3]);
            }
        }
    }

    // ---- epilogue: divide by l, write fp16 ----
    float inv0 = 1.0f / l0, inv1 = 1.0f / l1;
    #pragma unroll
    for (int nj = 0; nj < 8; nj++) {
        int col = nj * 8 + 2 * tig;
        __half* dst = &g_Oh[(size_t)(b * LQ + q0 + row0) * HID + h * DH + col];
        *(__half2*)dst = __floats2half2_rn(of[nj][0] * inv0, of[nj][1] * inv0);
        *(__half2*)(dst + (size_t)8 * HID) =
            __floats2half2_rn(of[nj][2] * inv1, of[nj][3] * inv1);
    }
}

// ---------------------------------------------------------------------------
// kernel_launch
// ---------------------------------------------------------------------------
extern "C" void kernel_launch(void* const* d_in, const int* in_sizes, int n_in,
                              void* d_out, int out_size) {
    (void)in_sizes; (void)n_in; (void)out_size;
    const float* query     = (const float*)d_in[0];
    const float* key_value = (const float*)d_in[1];
    const void*  mask      = d_in[2];
    const float* Wq = (const float*)d_in[3];
    const float* bq = (const float*)d_in[4];
    const float* Wk = (const float*)d_in[5];
    const float* bk = (const float*)d_in[6];
    const float* Wv = (const float*)d_in[7];
    const float* bv = (const float*)d_in[8];
    const float* Wo = (const float*)d_in[9];
    const float* bo = (const float*)d_in[10];
    float* out = (float*)d_out;

    __half *Qp, *KVp, *Qh, *KVh, *Oh, *WqT, *WkvT, *WoT;
    float  *bkv;
    cudaGetSymbolAddress((void**)&Qp,   g_Qp);
    cudaGetSymbolAddress((void**)&KVp,  g_KVp);
    cudaGetSymbolAddress((void**)&Qh,   g_Qh);
    cudaGetSymbolAddress((void**)&KVh,  g_KVh);
    cudaGetSymbolAddress((void**)&Oh,   g_Oh);
    cudaGetSymbolAddress((void**)&WqT,  g_WqT);
    cudaGetSymbolAddress((void**)&WkvT, g_WkvT);
    cudaGetSymbolAddress((void**)&WoT,  g_WoT);
    cudaGetSymbolAddress((void**)&bkv,  g_bkv);

    // mask -> additive bias (exp2 domain)
    detect_mask_kind_kernel<<<1, 256>>>((const unsigned int*)mask);
    build_bias_kernel<<<(B_ * LKV + 255) / 256, 256>>>(mask);
    concat_bias<<<(HID + 255) / 256, 256>>>(bk, bv);

    // prep: fp16 activations; fp16 transposed weights [N][K]
    const int TPB = 256;
    int n4;
    n4 = (B_ * LQ * QDIM) / 4;
    to_half<<<(n4 + TPB - 1) / TPB, TPB>>>(query, Qh, n4);
    n4 = (B_ * LKV * KVDIM) / 4;
    to_half<<<(n4 + TPB - 1) / TPB, TPB>>>(key_value, KVh, n4);
    dim3 tb(32, 8);
    transpose_half<<<dim3(HID / 32, QDIM / 32), tb>>>(Wq, WqT, QDIM, HID);
    transpose_half<<<dim3(HID / 32, KVDIM / 32), tb>>>(Wk, WkvT, KVDIM, HID);
    transpose_half<<<dim3(HID / 32, KVDIM / 32), tb>>>(
        Wv, WkvT + (size_t)HID * KVDIM, KVDIM, HID);
    transpose_half<<<dim3(HID / 32, HID / 32), tb>>>(Wo, WoT, HID, HID);

    // projections: Q (N=1024) and merged K|V (N=2048)
    dim3 gq(HID / 128, (B_ * LQ) / 128);     // (8, 32)
    dim3 gkv(KVW / 128, (B_ * LKV) / 128);   // (16, 128)
    gemm_f16<<<gq, 256>>>(Qh, WqT, bq, nullptr, Qp, B_ * LQ, HID, QDIM);
    gemm_f16<<<gkv, 256>>>(KVh, WkvT, bkv, nullptr, KVp, B_ * LKV, KVW, KVDIM);

    // fused attention (fp16 mma, register P, exp2 softmax)
    attn_f16<<<dim3(LQ / 128, B_ * NH), 256>>>();

    // output projection (fp16 GEMM, fp32 output)
    gemm_f16<<<gq, 256>>>(Oh, WoT, bo, out, nullptr, B_ * LQ, HID, HID);
}

// round 15
// speedup vs baseline: 1.5217x; 1.5217x over previous
#include <cuda_runtime.h>
#include <cuda_fp16.h>
#include <math.h>
#include <stdint.h>

// Problem constants
#define B_    8
#define LQ    512
#define LKV   2048
#define QDIM  768
#define KVDIM 768
#define HID   1024
#define NH    16
#define DH    64
#define KVW   2048    // merged K|V projection row width

// ---------------------------------------------------------------------------
// Scratch (device globals)
// ---------------------------------------------------------------------------
__device__ __half g_Qp[(size_t)B_ * LQ * HID];     // projected Q (fp16)
__device__ __half g_KVp[(size_t)B_ * LKV * KVW];   // projected [K|V] (compact)
__device__ __half g_Oh[(size_t)B_ * LQ * HID];     // attention out (fp16)
__device__ float  g_cbias[B_ * LKV];               // compact bias (0 / -inf2)
__device__ float  g_bkv[KVW];                      // [bk|bv] concatenated
__device__ int    g_mask_kind;
__device__ int    g_idx[B_ * LKV];                 // compact -> original kv idx
__device__ int    g_cnt[B_];                       // valid count per batch
__device__ int    g_jmax[B_];                      // ceil64(cnt)
__device__ int    g_cpad[B_];                      // ceil128(cnt)
// fp16 prep buffers
__device__ __half g_Qh[(size_t)B_ * LQ * QDIM];    // query fp16 [M][K]
__device__ __half g_KVh[(size_t)B_ * LKV * KVDIM]; // compacted key_value fp16
__device__ __half g_WqT[QDIM * HID];               // Wq^T fp16 [N][K]
__device__ __half g_WkvT[(size_t)KVW * KVDIM];     // [Wk^T | Wv^T] fp16
__device__ __half g_WoT[HID * HID];

// ---------------------------------------------------------------------------
// Helpers
// ---------------------------------------------------------------------------
__device__ __forceinline__ void mma_f16(float d[4], const uint32_t a[4],
                                        uint32_t b0, uint32_t b1) {
    asm volatile(
        "mma.sync.aligned.m16n8k16.row.col.f32.f16.f16.f32 "
        "{%0,%1,%2,%3}, {%4,%5,%6,%7}, {%8,%9}, {%0,%1,%2,%3};\n"
        : "+f"(d[0]), "+f"(d[1]), "+f"(d[2]), "+f"(d[3])
        : "r"(a[0]), "r"(a[1]), "r"(a[2]), "r"(a[3]), "r"(b0), "r"(b1));
}

#define LDSM_X4(r, addr)                                                      \
    asm volatile("ldmatrix.sync.aligned.m8n8.x4.shared.b16 {%0,%1,%2,%3}, [%4];" \
                 : "=r"((r)[0]), "=r"((r)[1]), "=r"((r)[2]), "=r"((r)[3])     \
                 : "r"(addr))

#define LDSM_X4_T(r, addr)                                                    \
    asm volatile("ldmatrix.sync.aligned.m8n8.x4.trans.shared.b16 {%0,%1,%2,%3}, [%4];" \
                 : "=r"((r)[0]), "=r"((r)[1]), "=r"((r)[2]), "=r"((r)[3])     \
                 : "r"(addr))

__device__ __forceinline__ void cp16(uint32_t dst_smem, const void* src) {
    asm volatile("cp.async.cg.shared.global [%0], [%1], 16;\n"
                 :: "r"(dst_smem), "l"(src));
}

__device__ __forceinline__ uint32_t smem_u32(const void* p) {
    uint32_t a;
    asm("{ .reg .u64 t; cvta.to.shared.u64 t, %1; cvt.u32.u64 %0, t; }"
        : "=r"(a) : "l"(p));
    return a;
}

__device__ __forceinline__ uint32_t ph2(float lo, float hi) {
    __half2 h = __floats2half2_rn(lo, hi);
    return *reinterpret_cast<uint32_t*>(&h);
}

// ---------------------------------------------------------------------------
// Prep kernels
// ---------------------------------------------------------------------------
__global__ void to_half(const float* __restrict__ s, __half* __restrict__ d,
                        int n4) {
    for (int i = blockIdx.x * blockDim.x + threadIdx.x; i < n4;
         i += gridDim.x * blockDim.x) {
        float4 v = ((const float4*)s)[i];
        ((__half2*)d)[i * 2]     = __floats2half2_rn(v.x, v.y);
        ((__half2*)d)[i * 2 + 1] = __floats2half2_rn(v.z, v.w);
    }
}

// W[K][N] fp32 -> WT[N][K] fp16. block (32,8), grid (N/32, K/32).
__global__ void transpose_half(const float* __restrict__ s,
                               __half* __restrict__ d, int K, int N) {
    __shared__ float t[32][33];
    int n0 = blockIdx.x * 32, k0 = blockIdx.y * 32;
    int tx = threadIdx.x, ty = threadIdx.y;
    #pragma unroll
    for (int i = 0; i < 32; i += 8)
        t[ty + i][tx] = s[(size_t)(k0 + ty + i) * N + n0 + tx];
    __syncthreads();
    #pragma unroll
    for (int i = 0; i < 32; i += 8)
        d[(size_t)(n0 + ty + i) * K + k0 + tx] = __float2half(t[tx][ty + i]);
}

__global__ void concat_bias(const float* __restrict__ a,
                            const float* __restrict__ b) {
    int i = blockIdx.x * blockDim.x + threadIdx.x;
    if (i < HID) { g_bkv[i] = a[i]; g_bkv[HID + i] = b[i]; }
}

// ---------------------------------------------------------------------------
// Mask dtype classification
// ---------------------------------------------------------------------------
__global__ void detect_mask_kind_kernel(const unsigned int* __restrict__ w) {
    __shared__ int bad_f32, bad_i32;
    if (threadIdx.x == 0) { bad_f32 = 0; bad_i32 = 0; }
    __syncthreads();
    int lf = 0, li = 0;
    for (int i = threadIdx.x; i < (B_ * LKV) / 4; i += blockDim.x) {
        unsigned int x = w[i];
        if (!(x == 0u || x == 0x3f800000u)) lf = 1;
        if (!(x == 0u || x == 1u))          li = 1;
    }
    if (lf) bad_f32 = 1;
    if (li) bad_i32 = 1;
    __syncthreads();
    if (threadIdx.x == 0)
        g_mask_kind = (!bad_f32) ? 0 : ((!bad_i32) ? 1 : 2);
}

// ---------------------------------------------------------------------------
// Mask compaction: one block (256 threads) per batch.
// Each thread owns 8 consecutive positions; block-wide exclusive scan gives
// deterministic ascending compact indices. Also writes cnt / jmax / cpad and
// the compact-domain bias (only pad slots masked).
// ---------------------------------------------------------------------------
__global__ void compact_mask(const void* __restrict__ mp) {
    __shared__ int wsum[8];
    __shared__ int s_total;
    const int b    = blockIdx.x;
    const int tid  = threadIdx.x;
    const int lane = tid & 31;
    const int wid  = tid >> 5;
    const int kind = g_mask_kind;
    const int base = b * LKV + tid * 8;

    bool v[8];
    int lc = 0;
    #pragma unroll
    for (int i = 0; i < 8; i++) {
        bool on;
        if (kind == 0)      on = (((const float*)mp)[base + i] != 0.0f);
        else if (kind == 1) on = (((const int*)mp)[base + i] != 0);
        else                on = (((const unsigned char*)mp)[base + i] != 0);
        v[i] = on;
        lc += on;
    }
    // warp-level exclusive scan of per-thread counts
    int pre = lc;
    #pragma unroll
    for (int d = 1; d < 32; d <<= 1) {
        int t = __shfl_up_sync(0xffffffffu, pre, d);
        if (lane >= d) pre += t;
    }
    int warp_total = __shfl_sync(0xffffffffu, pre, 31);
    int excl = pre - lc;
    if (lane == 31) wsum[wid] = warp_total;
    __syncthreads();
    if (wid == 0) {
        int wv = (lane < 8) ? wsum[lane] : 0;
        #pragma unroll
        for (int d = 1; d < 8; d <<= 1) {
            int t = __shfl_up_sync(0xffffffffu, wv, d);
            if (lane >= d) wv += t;
        }
        if (lane < 8) wsum[lane] = wv;   // inclusive warp prefix
        if (lane == 7) s_total = wv;
    }
    __syncthreads();
    int off = excl + (wid > 0 ? wsum[wid - 1] : 0);
    #pragma unroll
    for (int i = 0; i < 8; i++)
        if (v[i]) g_idx[b * LKV + off++] = tid * 8 + i;

    const int total = s_total;
    if (tid == 0) {
        g_cnt[b]  = total;
        g_jmax[b] = (total + 63) & ~63;
        g_cpad[b] = (total + 127) & ~127;
    }
    // compact bias: 0 for valid slots, -inf2 for pads (exp2 domain)
    for (int j = tid; j < LKV; j += 256)
        g_cbias[b * LKV + j] = (j < total) ? 0.0f : -1.4426950e30f;
}

// ---------------------------------------------------------------------------
// Gather + fp32->fp16 convert of valid kv rows into compact order.
// Rows [cnt, cpad) zeroed (projection then yields pure-bias rows, which the
// compact bias masks). Rows >= cpad untouched (GEMM skips those tiles).
// 8 floats per thread; grid covers B * LKV * KVDIM/8 threads.
// ---------------------------------------------------------------------------
__global__ void gather_half(const float* __restrict__ kv) {
    int t = blockIdx.x * blockDim.x + threadIdx.x;
    const int perrow = KVDIM / 8;                  // 96
    int b = t / (LKV * perrow);
    int rem = t % (LKV * perrow);
    int r = rem / perrow;
    int c = (rem % perrow) * 8;
    if (b >= B_) return;
    if (r >= g_cpad[b]) return;
    __half* dst = g_KVh + ((size_t)(b * LKV + r)) * KVDIM + c;
    if (r < g_cnt[b]) {
        const float* src = kv + ((size_t)(b * LKV + g_idx[b * LKV + r])) * KVDIM + c;
        float4 v0 = *(const float4*)(src);
        float4 v1 = *(const float4*)(src + 4);
        ((__half2*)dst)[0] = __floats2half2_rn(v0.x, v0.y);
        ((__half2*)dst)[1] = __floats2half2_rn(v0.z, v0.w);
        ((__half2*)dst)[2] = __floats2half2_rn(v1.x, v1.y);
        ((__half2*)dst)[3] = __floats2half2_rn(v1.z, v1.w);
    } else {
        ((__half2*)dst)[0] = __half2half2(__float2half(0.0f));
        ((__half2*)dst)[1] = __half2half2(__float2half(0.0f));
        ((__half2*)dst)[2] = __half2half2(__float2half(0.0f));
        ((__half2*)dst)[3] = __half2half2(__float2half(0.0f));
    }
}

// ---------------------------------------------------------------------------
// FP16 tensor-core GEMM:  C[M,N] = A[M,K] @ BT[N,K]^T + bias[N]  (f32 accum)
// Block 128x128, 256 threads (8 warps, 2Mx4N), warp 64x32. K-tile 32 halves.
// 2-stage cp.async, single sync/iter; ldmatrix frags, 80 B stride.
// blockIdx.z selects a batch when bstride>0; tiles past dcnt[z] early-exit.
// Exactly one of Cf / Ch is non-null.
// ---------------------------------------------------------------------------
#define GSTAGE 10240   // 128 rows * 80 B

#define LOAD_F16(st, k0)                                                      \
    do {                                                                      \
        _Pragma("unroll")                                                     \
        for (int i = 0; i < 2; i++) {                                         \
            int idx = tid + i * 256;                                          \
            int r = idx >> 2, c = idx & 3;                                    \
            cp16(saA + (st) * GSTAGE + r * 80 + c * 16,                       \
                 A + (size_t)(bym + r) * K + (k0) + c * 8);                   \
            cp16(saB + (st) * GSTAGE + r * 80 + c * 16,                       \
                 BT + (size_t)(bxn + r) * K + (k0) + c * 8);                  \
        }                                                                     \
        asm volatile("cp.async.commit_group;\n" ::: "memory");                \
    } while (0)

__global__ __launch_bounds__(256, 2) void gemm_f16(
    const __half* __restrict__ A, const __half* __restrict__ BT,
    const float* __restrict__ bias, float* __restrict__ Cf,
    __half* __restrict__ Ch, int N, int K,
    const int* __restrict__ dcnt, int bstride)
{
    const int bym = blockIdx.y * 128;
    if (dcnt && bym >= dcnt[blockIdx.z]) return;

    __shared__ __align__(16) __half As[2][128][40];
    __shared__ __align__(16) __half Bs[2][128][40];

    const size_t boff = (size_t)blockIdx.z * bstride;
    A  += boff * K;
    if (Cf) Cf += boff * N;
    if (Ch) Ch += boff * N;

    const int tid  = threadIdx.x;
    const int lane = tid & 31;
    const int wid  = tid >> 5;
    const int g    = lane >> 2;
    const int tig  = lane & 3;
    const int wm   = (wid >> 2) * 64;
    const int wn   = (wid & 3) * 32;
    const int bxn  = blockIdx.x * 128;

    const uint32_t saA = smem_u32(&As[0][0][0]);
    const uint32_t saB = smem_u32(&Bs[0][0][0]);

    const int lr  = lane & 7;
    const int seg = lane >> 3;
    const uint32_t aOff = (uint32_t)(wm + lr + (seg & 1) * 8) * 80
                        + ((seg >> 1) & 1) * 16;
    const uint32_t bOff = (uint32_t)(wn + lr + ((seg >> 1) & 1) * 8) * 80
                        + (seg & 1) * 16;

    float acc[4][4][4];
    #pragma unroll
    for (int mi = 0; mi < 4; mi++)
        #pragma unroll
        for (int nj = 0; nj < 4; nj++)
            #pragma unroll
            for (int f = 0; f < 4; f++) acc[mi][nj][f] = 0.0f;

    const int T = K >> 5;
    LOAD_F16(0, 0);

    for (int t = 0; t < T; t++) {
        const int s = t & 1;
        asm volatile("cp.async.wait_group 0;\n" ::: "memory");
        __syncthreads();
        if (t + 1 < T) LOAD_F16(s ^ 1, (t + 1) << 5);

        const uint32_t aS = saA + s * GSTAGE + aOff;
        const uint32_t bS = saB + s * GSTAGE + bOff;
        #pragma unroll
        for (int ks = 0; ks < 2; ks++) {
            const uint32_t kb = ks * 32;
            uint32_t af[4][4], bf[2][4];
            #pragma unroll
            for (int mi = 0; mi < 4; mi++)
                LDSM_X4(af[mi], aS + mi * (16 * 80) + kb);
            #pragma unroll
            for (int p = 0; p < 2; p++)
                LDSM_X4(bf[p], bS + p * (16 * 80) + kb);
            #pragma unroll
            for (int mi = 0; mi < 4; mi++)
                #pragma unroll
                for (int nj = 0; nj < 4; nj++)
                    mma_f16(acc[mi][nj], af[mi],
                            bf[nj >> 1][(nj & 1) * 2],
                            bf[nj >> 1][(nj & 1) * 2 + 1]);
        }
    }

    #pragma unroll
    for (int mi = 0; mi < 4; mi++) {
        int row = bym + wm + mi * 16 + g;
        #pragma unroll
        for (int nj = 0; nj < 4; nj++) {
            int col = bxn + wn + nj * 8 + 2 * tig;
            float b0 = bias[col], b1 = bias[col + 1];
            float v00 = acc[mi][nj][0] + b0, v01 = acc[mi][nj][1] + b1;
            float v10 = acc[mi][nj][2] + b0, v11 = acc[mi][nj][3] + b1;
            if (Ch) {
                *(__half2*)&Ch[(size_t)row * N + col] =
                    __floats2half2_rn(v00, v01);
                *(__half2*)&Ch[(size_t)(row + 8) * N + col] =
                    __floats2half2_rn(v10, v11);
            } else {
                *(float2*)&Cf[(size_t)row * N + col] = make_float2(v00, v01);
                *(float2*)&Cf[(size_t)(row + 8) * N + col] =
                    make_float2(v10, v11);
            }
        }
    }
}

// ---------------------------------------------------------------------------
// Fused flash attention over the COMPACT kv sequence (length g_jmax[b]).
// fp16 mma (m16n8k16), register-resident P, exp2-domain softmax.
// grid = (LQ/128, B*NH), 256 threads (8 warps), warp owns 16 q-rows.
// 64-row KV tiles (128 B rows), smem stride 144 B, 2-stage cp.async.
// ---------------------------------------------------------------------------
#define ASTR 144
#define ASTG (64 * ASTR)
#define SC2  0.18033688f      // 0.125 * log2(e)

#define LOAD_KV(st, j0)                                                       \
    do {                                                                      \
        _Pragma("unroll")                                                     \
        for (int i = 0; i < 2; i++) {                                         \
            int idx = tid + i * 256;                                          \
            int r = idx >> 3, c = idx & 7;                                    \
            cp16(ks0 + (st) * ASTG + r * ASTR + c * 16,                       \
                 Kg + (size_t)((j0) + r) * KVW + c * 8);                      \
            cp16(vs0 + (st) * ASTG + r * ASTR + c * 16,                       \
                 Vg + (size_t)((j0) + r) * KVW + c * 8);                      \
        }                                                                     \
        asm volatile("cp.async.commit_group;\n" ::: "memory");                \
    } while (0)

__global__ __launch_bounds__(256) void attn_f16() {
    __shared__ __align__(16) __half Ks[2][64][ASTR / 2];
    __shared__ __align__(16) __half Vs[2][64][ASTR / 2];

    const int tid  = threadIdx.x;
    const int lane = tid & 31;
    const int w    = tid >> 5;
    const int g    = lane >> 2;
    const int tig  = lane & 3;
    const int lr   = lane & 7;
    const int seg  = lane >> 3;
    const int bh   = blockIdx.y;
    const int b    = bh >> 4;
    const int h    = bh & 15;
    const int q0   = blockIdx.x * 128;
    const int row0 = w * 16 + g;

    const __half* Qg = g_Qp + ((size_t)(b * LQ + q0)) * HID + h * DH;
    const __half* Kg = g_KVp + ((size_t)b * LKV) * KVW + h * DH;
    const __half* Vg = Kg + HID;
    const float*  bg = g_cbias + b * LKV;
    const int     ntiles = g_jmax[b] >> 6;

    const uint32_t ks0 = smem_u32(&Ks[0][0][0]);
    const uint32_t vs0 = smem_u32(&Vs[0][0][0]);

    const uint32_t kOff = (uint32_t)(lr + ((seg >> 1) & 1) * 8) * ASTR
                        + (seg & 1) * 16;
    const uint32_t vOff = (uint32_t)(lr + (seg & 1) * 8) * ASTR
                        + ((seg >> 1) & 1) * 16;

    // ---- Q fragments from gmem fp16 ----
    uint32_t qf[4][4];
    {
        const __half* q0p = Qg + (size_t)row0 * HID;
        const __half* q8p = Qg + (size_t)(row0 + 8) * HID;
        #pragma unroll
        for (int kk = 0; kk < 4; kk++) {
            int col = kk * 16 + 2 * tig;
            qf[kk][0] = *(const uint32_t*)(q0p + col);
            qf[kk][1] = *(const uint32_t*)(q8p + col);
            qf[kk][2] = *(const uint32_t*)(q0p + col + 8);
            qf[kk][3] = *(const uint32_t*)(q8p + col + 8);
        }
    }

    float of[8][4];
    #pragma unroll
    for (int nj = 0; nj < 8; nj++)
        #pragma unroll
        for (int f = 0; f < 4; f++) of[nj][f] = 0.0f;
    float m0 = -1.0e30f, m1 = -1.0e30f, l0 = 0.0f, l1 = 0.0f;

    LOAD_KV(0, 0);

    for (int t = 0; t < ntiles; t++) {
        const int s  = t & 1;
        const int j0 = t * 64;
        asm volatile("cp.async.wait_group 0;\n" ::: "memory");
        __syncthreads();
        if (t + 1 < ntiles) LOAD_KV(s ^ 1, j0 + 64);

        const uint32_t kS = ks0 + s * ASTG;
        const uint32_t vS = vs0 + s * ASTG;

        // ---- S = Q K^T ----
        float sv[8][4];
        #pragma unroll
        for (int nj = 0; nj < 8; nj++)
            #pragma unroll
            for (int f = 0; f < 4; f++) sv[nj][f] = 0.0f;
        #pragma unroll
        for (int kk = 0; kk < 4; kk++) {
            #pragma unroll
            for (int p = 0; p < 4; p++) {
                uint32_t bf[4];
                LDSM_X4(bf, kS + kOff + p * (16 * ASTR) + kk * 32);
                mma_f16(sv[2 * p],     qf[kk], bf[0], bf[1]);
                mma_f16(sv[2 * p + 1], qf[kk], bf[2], bf[3]);
            }
        }

        // ---- scale + pad bias (exp2 domain), online softmax ----
        float mx0 = -1.0e30f, mx1 = -1.0e30f;
        #pragma unroll
        for (int nj = 0; nj < 8; nj++) {
            float2 bb = *(const float2*)&bg[j0 + nj * 8 + 2 * tig];
            sv[nj][0] = sv[nj][0] * SC2 + bb.x;
            sv[nj][1] = sv[nj][1] * SC2 + bb.y;
            sv[nj][2] = sv[nj][2] * SC2 + bb.x;
            sv[nj][3] = sv[nj][3] * SC2 + bb.y;
            mx0 = fmaxf(mx0, fmaxf(sv[nj][0], sv[nj][1]));
            mx1 = fmaxf(mx1, fmaxf(sv[nj][2], sv[nj][3]));
        }
        mx0 = fmaxf(mx0, __shfl_xor_sync(0xffffffffu, mx0, 1));
        mx0 = fmaxf(mx0, __shfl_xor_sync(0xffffffffu, mx0, 2));
        mx1 = fmaxf(mx1, __shfl_xor_sync(0xffffffffu, mx1, 1));
        mx1 = fmaxf(mx1, __shfl_xor_sync(0xffffffffu, mx1, 2));
        float mn0 = fmaxf(m0, mx0), mn1 = fmaxf(m1, mx1);
        float c0 = exp2f(m0 - mn0), c1 = exp2f(m1 - mn1);
        m0 = mn0; m1 = mn1;

        float sum0 = 0.0f, sum1 = 0.0f;
        #pragma unroll
        for (int nj = 0; nj < 8; nj++) {
            sv[nj][0] = exp2f(sv[nj][0] - m0);
            sv[nj][1] = exp2f(sv[nj][1] - m0);
            sv[nj][2] = exp2f(sv[nj][2] - m1);
            sv[nj][3] = exp2f(sv[nj][3] - m1);
            sum0 += sv[nj][0] + sv[nj][1];
            sum1 += sv[nj][2] + sv[nj][3];
        }
        sum0 += __shfl_xor_sync(0xffffffffu, sum0, 1);
        sum0 += __shfl_xor_sync(0xffffffffu, sum0, 2);
        sum1 += __shfl_xor_sync(0xffffffffu, sum1, 1);
        sum1 += __shfl_xor_sync(0xffffffffu, sum1, 2);
        l0 = l0 * c0 + sum0;
        l1 = l1 * c1 + sum1;

        #pragma unroll
        for (int nj = 0; nj < 8; nj++) {
            of[nj][0] *= c0; of[nj][1] *= c0;
            of[nj][2] *= c1; of[nj][3] *= c1;
        }

        // ---- O += P V ----
        #pragma unroll
        for (int kk2 = 0; kk2 < 4; kk2++) {
            uint32_t pf[4];
            pf[0] = ph2(sv[2 * kk2][0],     sv[2 * kk2][1]);
            pf[1] = ph2(sv[2 * kk2][2],     sv[2 * kk2][3]);
            pf[2] = ph2(sv[2 * kk2 + 1][0], sv[2 * kk2 + 1][1]);
            pf[3] = ph2(sv[2 * kk2 + 1][2], sv[2 * kk2 + 1][3]);
            #pragma unroll
            for (int p2 = 0; p2 < 4; p2++) {
                uint32_t bf[4];
                LDSM_X4_T(bf, vS + vOff + kk2 * (16 * ASTR) + p2 * 32);
                mma_f16(of[2 * p2],     pf, bf[0], bf[1]);
                mma_f16(of[2 * p2 + 1], pf, bf[2], bf[3]);
            }
        }
    }

    // ---- epilogue ----
    float inv0 = 1.0f / l0, inv1 = 1.0f / l1;
    #pragma unroll
    for (int nj = 0; nj < 8; nj++) {
        int col = nj * 8 + 2 * tig;
        __half* dst = &g_Oh[(size_t)(b * LQ + q0 + row0) * HID + h * DH + col];
        *(__half2*)dst = __floats2half2_rn(of[nj][0] * inv0, of[nj][1] * inv0);
        *(__half2*)(dst + (size_t)8 * HID) =
            __floats2half2_rn(of[nj][2] * inv1, of[nj][3] * inv1);
    }
}

// ---------------------------------------------------------------------------
// kernel_launch
// ---------------------------------------------------------------------------
extern "C" void kernel_launch(void* const* d_in, const int* in_sizes, int n_in,
                              void* d_out, int out_size) {
    (void)in_sizes; (void)n_in; (void)out_size;
    const float* query     = (const float*)d_in[0];
    const float* key_value = (const float*)d_in[1];
    const void*  mask      = d_in[2];
    const float* Wq = (const float*)d_in[3];
    const float* bq = (const float*)d_in[4];
    const float* Wk = (const float*)d_in[5];
    const float* bk = (const float*)d_in[6];
    const float* Wv = (const float*)d_in[7];
    const float* bv = (const float*)d_in[8];
    const float* Wo = (const float*)d_in[9];
    const float* bo = (const float*)d_in[10];
    float* out = (float*)d_out;

    __half *Qp, *KVp, *Qh, *KVh, *Oh, *WqT, *WkvT, *WoT;
    float  *bkv;
    int    *cpad;
    cudaGetSymbolAddress((void**)&Qp,   g_Qp);
    cudaGetSymbolAddress((void**)&KVp,  g_KVp);
    cudaGetSymbolAddress((void**)&Qh,   g_Qh);
    cudaGetSymbolAddress((void**)&KVh,  g_KVh);
    cudaGetSymbolAddress((void**)&Oh,   g_Oh);
    cudaGetSymbolAddress((void**)&WqT,  g_WqT);
    cudaGetSymbolAddress((void**)&WkvT, g_WkvT);
    cudaGetSymbolAddress((void**)&WoT,  g_WoT);
    cudaGetSymbolAddress((void**)&bkv,  g_bkv);
    cudaGetSymbolAddress((void**)&cpad, g_cpad);

    // mask detection -> compaction (idx/cnt/jmax/cpad/compact bias)
    detect_mask_kind_kernel<<<1, 256>>>((const unsigned int*)mask);
    compact_mask<<<B_, 256>>>(mask);
    concat_bias<<<(HID + 255) / 256, 256>>>(bk, bv);

    // prep: fp16 query; gathered+converted compact KV; fp16 W^T
    const int TPB = 256;
    int n4 = (B_ * LQ * QDIM) / 4;
    to_half<<<(n4 + TPB - 1) / TPB, TPB>>>(query, Qh, n4);
    int ng = B_ * LKV * (KVDIM / 8);
    gather_half<<<(ng + TPB - 1) / TPB, TPB>>>(key_value);
    dim3 tb(32, 8);
    transpose_half<<<dim3(HID / 32, QDIM / 32), tb>>>(Wq, WqT, QDIM, HID);
    transpose_half<<<dim3(HID / 32, KVDIM / 32), tb>>>(Wk, WkvT, KVDIM, HID);
    transpose_half<<<dim3(HID / 32, KVDIM / 32), tb>>>(
        Wv, WkvT + (size_t)HID * KVDIM, KVDIM, HID);
    transpose_half<<<dim3(HID / 32, HID / 32), tb>>>(Wo, WoT, HID, HID);

    // projections: Q (dense) and merged K|V over compact rows (per-batch z)
    dim3 gq(HID / 128, (B_ * LQ) / 128, 1);     // (8, 32, 1)
    dim3 gkv(KVW / 128, LKV / 128, B_);         // (16, 16, 8)
    gemm_f16<<<gq, 256>>>(Qh, WqT, bq, nullptr, Qp, HID, QDIM, nullptr, 0);
    gemm_f16<<<gkv, 256>>>(KVh, WkvT, bkv, nullptr, KVp, KVW, KVDIM,
                           cpad, LKV);

    // fused attention over compact kv
    attn_f16<<<dim3(LQ / 128, B_ * NH), 256>>>();

    // output projection (fp32 output)
    gemm_f16<<<gq, 256>>>(Oh, WoT, bo, out, nullptr, HID, HID, nullptr, 0);
}

// round 16
// speedup vs baseline: 1.6158x; 1.0618x over previous
#include <cuda_runtime.h>
#include <cuda_fp16.h>
#include <math.h>
#include <stdint.h>

// Problem constants
#define B_    8
#define LQ    512
#define LKV   2048
#define QDIM  768
#define KVDIM 768
#define HID   1024
#define NH    16
#define DH    64
#define KVW   2048    // merged K|V projection row width

// ---------------------------------------------------------------------------
// Scratch (device globals)
// ---------------------------------------------------------------------------
__device__ __half g_Qp[(size_t)B_ * LQ * HID];     // projected Q (fp16)
__device__ __half g_KVp[(size_t)B_ * LKV * KVW];   // projected [K|V] (compact)
__device__ __half g_Oh[(size_t)B_ * LQ * HID];     // attention out (fp16)
__device__ float  g_cbias[B_ * LKV];               // compact bias (0 / -inf2)
__device__ float  g_bkv[KVW];                      // [bk|bv] concatenated
__device__ int    g_idx[B_ * LKV];                 // compact -> original kv idx
__device__ int    g_cnt[B_];                       // valid count per batch
__device__ int    g_jmax[B_];                      // ceil64(cnt)
__device__ int    g_cpad[B_];                      // ceil128(cnt)
// fp16 prep buffers
__device__ __half g_Qh[(size_t)B_ * LQ * QDIM];    // query fp16 [M][K]
__device__ __half g_KVh[(size_t)B_ * LKV * KVDIM]; // compacted key_value fp16
__device__ __half g_WqT[QDIM * HID];               // Wq^T fp16 [N][K]
__device__ __half g_WkvT[(size_t)KVW * KVDIM];     // [Wk^T | Wv^T] fp16
__device__ __half g_WoT[HID * HID];

// ---------------------------------------------------------------------------
// Helpers
// ---------------------------------------------------------------------------
__device__ __forceinline__ void mma_f16(float d[4], const uint32_t a[4],
                                        uint32_t b0, uint32_t b1) {
    asm volatile(
        "mma.sync.aligned.m16n8k16.row.col.f32.f16.f16.f32 "
        "{%0,%1,%2,%3}, {%4,%5,%6,%7}, {%8,%9}, {%0,%1,%2,%3};\n"
        : "+f"(d[0]), "+f"(d[1]), "+f"(d[2]), "+f"(d[3])
        : "r"(a[0]), "r"(a[1]), "r"(a[2]), "r"(a[3]), "r"(b0), "r"(b1));
}

#define LDSM_X4(r, addr)                                                      \
    asm volatile("ldmatrix.sync.aligned.m8n8.x4.shared.b16 {%0,%1,%2,%3}, [%4];" \
                 : "=r"((r)[0]), "=r"((r)[1]), "=r"((r)[2]), "=r"((r)[3])     \
                 : "r"(addr))

#define LDSM_X4_T(r, addr)                                                    \
    asm volatile("ldmatrix.sync.aligned.m8n8.x4.trans.shared.b16 {%0,%1,%2,%3}, [%4];" \
                 : "=r"((r)[0]), "=r"((r)[1]), "=r"((r)[2]), "=r"((r)[3])     \
                 : "r"(addr))

__device__ __forceinline__ void cp16(uint32_t dst_smem, const void* src) {
    asm volatile("cp.async.cg.shared.global [%0], [%1], 16;\n"
                 :: "r"(dst_smem), "l"(src));
}

__device__ __forceinline__ uint32_t smem_u32(const void* p) {
    uint32_t a;
    asm("{ .reg .u64 t; cvta.to.shared.u64 t, %1; cvt.u32.u64 %0, t; }"
        : "=r"(a) : "l"(p));
    return a;
}

__device__ __forceinline__ uint32_t ph2(float lo, float hi) {
    __half2 h = __floats2half2_rn(lo, hi);
    return *reinterpret_cast<uint32_t*>(&h);
}

// ---------------------------------------------------------------------------
// Prep kernels
// ---------------------------------------------------------------------------
__global__ void to_half(const float* __restrict__ s, __half* __restrict__ d,
                        int n4) {
    for (int i = blockIdx.x * blockDim.x + threadIdx.x; i < n4;
         i += gridDim.x * blockDim.x) {
        float4 v = ((const float4*)s)[i];
        ((__half2*)d)[i * 2]     = __floats2half2_rn(v.x, v.y);
        ((__half2*)d)[i * 2 + 1] = __floats2half2_rn(v.z, v.w);
    }
}

// W[K][N] fp32 -> WT[N][K] fp16. block (32,8), grid (N/32, K/32).
__global__ void transpose_half(const float* __restrict__ s,
                               __half* __restrict__ d, int K, int N) {
    __shared__ float t[32][33];
    int n0 = blockIdx.x * 32, k0 = blockIdx.y * 32;
    int tx = threadIdx.x, ty = threadIdx.y;
    #pragma unroll
    for (int i = 0; i < 32; i += 8)
        t[ty + i][tx] = s[(size_t)(k0 + ty + i) * N + n0 + tx];
    __syncthreads();
    #pragma unroll
    for (int i = 0; i < 32; i += 8)
        d[(size_t)(n0 + ty + i) * K + k0 + tx] = __float2half(t[tx][ty + i]);
}

// ---------------------------------------------------------------------------
// Mask compaction: one block (256 threads) per batch. Self-classifies the
// mask dtype (from the buffer's first 4KB: identical result in every block),
// block-scans to deterministic ascending compact indices, writes
// cnt/jmax/cpad and the compact-domain pad bias. Block 0 also concats bk|bv.
// ---------------------------------------------------------------------------
__global__ void compact_mask(const void* __restrict__ mp,
                             const float* __restrict__ bk,
                             const float* __restrict__ bv) {
    __shared__ int wsum[8];
    __shared__ int s_total;
    __shared__ int sbad[2];
    const int b    = blockIdx.x;
    const int tid  = threadIdx.x;
    const int lane = tid & 31;
    const int wid  = tid >> 5;

    // classify dtype from first 1024 words (same answer in all blocks)
    if (tid == 0) { sbad[0] = 0; sbad[1] = 0; }
    __syncthreads();
    {
        const unsigned int* wds = (const unsigned int*)mp;
        int lf = 0, li = 0;
        for (int i = tid; i < 1024; i += 256) {
            unsigned int x = wds[i];
            if (!(x == 0u || x == 0x3f800000u)) lf = 1;
            if (!(x == 0u || x == 1u))          li = 1;
        }
        if (lf) sbad[0] = 1;
        if (li) sbad[1] = 1;
    }
    __syncthreads();
    const int kind = (!sbad[0]) ? 0 : ((!sbad[1]) ? 1 : 2);

    const int base = b * LKV + tid * 8;
    bool v[8];
    int lc = 0;
    #pragma unroll
    for (int i = 0; i < 8; i++) {
        bool on;
        if (kind == 0)      on = (((const float*)mp)[base + i] != 0.0f);
        else if (kind == 1) on = (((const int*)mp)[base + i] != 0);
        else                on = (((const unsigned char*)mp)[base + i] != 0);
        v[i] = on;
        lc += on;
    }
    // warp-level exclusive scan of per-thread counts
    int pre = lc;
    #pragma unroll
    for (int d = 1; d < 32; d <<= 1) {
        int t = __shfl_up_sync(0xffffffffu, pre, d);
        if (lane >= d) pre += t;
    }
    int warp_total = __shfl_sync(0xffffffffu, pre, 31);
    int excl = pre - lc;
    if (lane == 31) wsum[wid] = warp_total;
    __syncthreads();
    if (wid == 0) {
        int wv = (lane < 8) ? wsum[lane] : 0;
        #pragma unroll
        for (int d = 1; d < 8; d <<= 1) {
            int t = __shfl_up_sync(0xffffffffu, wv, d);
            if (lane >= d) wv += t;
        }
        if (lane < 8) wsum[lane] = wv;   // inclusive warp prefix
        if (lane == 7) s_total = wv;
    }
    __syncthreads();
    int off = excl + (wid > 0 ? wsum[wid - 1] : 0);
    #pragma unroll
    for (int i = 0; i < 8; i++)
        if (v[i]) g_idx[b * LKV + off++] = tid * 8 + i;

    const int total = s_total;
    if (tid == 0) {
        g_cnt[b]  = total;
        g_jmax[b] = (total + 63) & ~63;
        g_cpad[b] = (total + 127) & ~127;
    }
    // compact bias: 0 for valid slots, -inf2 for pads (exp2 domain)
    for (int j = tid; j < LKV; j += 256)
        g_cbias[b * LKV + j] = (j < total) ? 0.0f : -1.4426950e30f;
    // block 0 concatenates the K|V projection bias
    if (b == 0)
        for (int i = tid; i < HID; i += 256) {
            g_bkv[i] = bk[i];
            g_bkv[HID + i] = bv[i];
        }
}

// ---------------------------------------------------------------------------
// Gather + fp32->fp16 convert of valid kv rows into compact order.
// ---------------------------------------------------------------------------
__global__ void gather_half(const float* __restrict__ kv) {
    int t = blockIdx.x * blockDim.x + threadIdx.x;
    const int perrow = KVDIM / 8;                  // 96
    int b = t / (LKV * perrow);
    int rem = t % (LKV * perrow);
    int r = rem / perrow;
    int c = (rem % perrow) * 8;
    if (b >= B_) return;
    if (r >= g_cpad[b]) return;
    __half* dst = g_KVh + ((size_t)(b * LKV + r)) * KVDIM + c;
    if (r < g_cnt[b]) {
        const float* src = kv + ((size_t)(b * LKV + g_idx[b * LKV + r])) * KVDIM + c;
        float4 v0 = *(const float4*)(src);
        float4 v1 = *(const float4*)(src + 4);
        ((__half2*)dst)[0] = __floats2half2_rn(v0.x, v0.y);
        ((__half2*)dst)[1] = __floats2half2_rn(v0.z, v0.w);
        ((__half2*)dst)[2] = __floats2half2_rn(v1.x, v1.y);
        ((__half2*)dst)[3] = __floats2half2_rn(v1.z, v1.w);
    } else {
        ((__half2*)dst)[0] = __half2half2(__float2half(0.0f));
        ((__half2*)dst)[1] = __half2half2(__float2half(0.0f));
        ((__half2*)dst)[2] = __half2half2(__float2half(0.0f));
        ((__half2*)dst)[3] = __half2half2(__float2half(0.0f));
    }
}

// ---------------------------------------------------------------------------
// FP16 tensor-core GEMM (unchanged, hardware-validated).
// ---------------------------------------------------------------------------
#define GSTAGE 10240   // 128 rows * 80 B

#define LOAD_F16(st, k0)                                                      \
    do {                                                                      \
        _Pragma("unroll")                                                     \
        for (int i = 0; i < 2; i++) {                                         \
            int idx = tid + i * 256;                                          \
            int r = idx >> 2, c = idx & 3;                                    \
            cp16(saA + (st) * GSTAGE + r * 80 + c * 16,                       \
                 A + (size_t)(bym + r) * K + (k0) + c * 8);                   \
            cp16(saB + (st) * GSTAGE + r * 80 + c * 16,                       \
                 BT + (size_t)(bxn + r) * K + (k0) + c * 8);                  \
        }                                                                     \
        asm volatile("cp.async.commit_group;\n" ::: "memory");                \
    } while (0)

__global__ __launch_bounds__(256, 2) void gemm_f16(
    const __half* __restrict__ A, const __half* __restrict__ BT,
    const float* __restrict__ bias, float* __restrict__ Cf,
    __half* __restrict__ Ch, int N, int K,
    const int* __restrict__ dcnt, int bstride)
{
    const int bym = blockIdx.y * 128;
    if (dcnt && bym >= dcnt[blockIdx.z]) return;

    __shared__ __align__(16) __half As[2][128][40];
    __shared__ __align__(16) __half Bs[2][128][40];

    const size_t boff = (size_t)blockIdx.z * bstride;
    A  += boff * K;
    if (Cf) Cf += boff * N;
    if (Ch) Ch += boff * N;

    const int tid  = threadIdx.x;
    const int lane = tid & 31;
    const int wid  = tid >> 5;
    const int g    = lane >> 2;
    const int tig  = lane & 3;
    const int wm   = (wid >> 2) * 64;
    const int wn   = (wid & 3) * 32;
    const int bxn  = blockIdx.x * 128;

    const uint32_t saA = smem_u32(&As[0][0][0]);
    const uint32_t saB = smem_u32(&Bs[0][0][0]);

    const int lr  = lane & 7;
    const int seg = lane >> 3;
    const uint32_t aOff = (uint32_t)(wm + lr + (seg & 1) * 8) * 80
                        + ((seg >> 1) & 1) * 16;
    const uint32_t bOff = (uint32_t)(wn + lr + ((seg >> 1) & 1) * 8) * 80
                        + (seg & 1) * 16;

    float acc[4][4][4];
    #pragma unroll
    for (int mi = 0; mi < 4; mi++)
        #pragma unroll
        for (int nj = 0; nj < 4; nj++)
            #pragma unroll
            for (int f = 0; f < 4; f++) acc[mi][nj][f] = 0.0f;

    const int T = K >> 5;
    LOAD_F16(0, 0);

    for (int t = 0; t < T; t++) {
        const int s = t & 1;
        asm volatile("cp.async.wait_group 0;\n" ::: "memory");
        __syncthreads();
        if (t + 1 < T) LOAD_F16(s ^ 1, (t + 1) << 5);

        const uint32_t aS = saA + s * GSTAGE + aOff;
        const uint32_t bS = saB + s * GSTAGE + bOff;
        #pragma unroll
        for (int ks = 0; ks < 2; ks++) {
            const uint32_t kb = ks * 32;
            uint32_t af[4][4], bf[2][4];
            #pragma unroll
            for (int mi = 0; mi < 4; mi++)
                LDSM_X4(af[mi], aS + mi * (16 * 80) + kb);
            #pragma unroll
            for (int p = 0; p < 2; p++)
                LDSM_X4(bf[p], bS + p * (16 * 80) + kb);
            #pragma unroll
            for (int mi = 0; mi < 4; mi++)
                #pragma unroll
                for (int nj = 0; nj < 4; nj++)
                    mma_f16(acc[mi][nj], af[mi],
                            bf[nj >> 1][(nj & 1) * 2],
                            bf[nj >> 1][(nj & 1) * 2 + 1]);
        }
    }

    #pragma unroll
    for (int mi = 0; mi < 4; mi++) {
        int row = bym + wm + mi * 16 + g;
        #pragma unroll
        for (int nj = 0; nj < 4; nj++) {
            int col = bxn + wn + nj * 8 + 2 * tig;
            float b0 = bias[col], b1 = bias[col + 1];
            float v00 = acc[mi][nj][0] + b0, v01 = acc[mi][nj][1] + b1;
            float v10 = acc[mi][nj][2] + b0, v11 = acc[mi][nj][3] + b1;
            if (Ch) {
                *(__half2*)&Ch[(size_t)row * N + col] =
                    __floats2half2_rn(v00, v01);
                *(__half2*)&Ch[(size_t)(row + 8) * N + col] =
                    __floats2half2_rn(v10, v11);
            } else {
                *(float2*)&Cf[(size_t)row * N + col] = make_float2(v00, v01);
                *(float2*)&Cf[(size_t)(row + 8) * N + col] =
                    make_float2(v10, v11);
            }
        }
    }
}

// ---------------------------------------------------------------------------
// Fused flash attention over the COMPACT kv sequence (unchanged).
// ---------------------------------------------------------------------------
#define ASTR 144
#define ASTG (64 * ASTR)
#define SC2  0.18033688f      // 0.125 * log2(e)

#define LOAD_KV(st, j0)                                                       \
    do {                                                                      \
        _Pragma("unroll")                                                     \
        for (int i = 0; i < 2; i++) {                                         \
            int idx = tid + i * 256;                                          \
            int r = idx >> 3, c = idx & 7;                                    \
            cp16(ks0 + (st) * ASTG + r * ASTR + c * 16,                       \
                 Kg + (size_t)((j0) + r) * KVW + c * 8);                      \
            cp16(vs0 + (st) * ASTG + r * ASTR + c * 16,                       \
                 Vg + (size_t)((j0) + r) * KVW + c * 8);                      \
        }                                                                     \
        asm volatile("cp.async.commit_group;\n" ::: "memory");                \
    } while (0)

__global__ __launch_bounds__(256) void attn_f16() {
    __shared__ __align__(16) __half Ks[2][64][ASTR / 2];
    __shared__ __align__(16) __half Vs[2][64][ASTR / 2];

    const int tid  = threadIdx.x;
    const int lane = tid & 31;
    const int w    = tid >> 5;
    const int g    = lane >> 2;
    const int tig  = lane & 3;
    const int lr   = lane & 7;
    const int seg  = lane >> 3;
    const int bh   = blockIdx.y;
    const int b    = bh >> 4;
    const int h    = bh & 15;
    const int q0   = blockIdx.x * 128;
    const int row0 = w * 16 + g;

    const __half* Qg = g_Qp + ((size_t)(b * LQ + q0)) * HID + h * DH;
    const __half* Kg = g_KVp + ((size_t)b * LKV) * KVW + h * DH;
    const __half* Vg = Kg + HID;
    const float*  bg = g_cbias + b * LKV;
    const int     ntiles = g_jmax[b] >> 6;

    const uint32_t ks0 = smem_u32(&Ks[0][0][0]);
    const uint32_t vs0 = smem_u32(&Vs[0][0][0]);

    const uint32_t kOff = (uint32_t)(lr + ((seg >> 1) & 1) * 8) * ASTR
                        + (seg & 1) * 16;
    const uint32_t vOff = (uint32_t)(lr + (seg & 1) * 8) * ASTR
                        + ((seg >> 1) & 1) * 16;

    uint32_t qf[4][4];
    {
        const __half* q0p = Qg + (size_t)row0 * HID;
        const __half* q8p = Qg + (size_t)(row0 + 8) * HID;
        #pragma unroll
        for (int kk = 0; kk < 4; kk++) {
            int col = kk * 16 + 2 * tig;
            qf[kk][0] = *(const uint32_t*)(q0p + col);
            qf[kk][1] = *(const uint32_t*)(q8p + col);
            qf[kk][2] = *(const uint32_t*)(q0p + col + 8);
            qf[kk][3] = *(const uint32_t*)(q8p + col + 8);
        }
    }

    float of[8][4];
    #pragma unroll
    for (int nj = 0; nj < 8; nj++)
        #pragma unroll
        for (int f = 0; f < 4; f++) of[nj][f] = 0.0f;
    float m0 = -1.0e30f, m1 = -1.0e30f, l0 = 0.0f, l1 = 0.0f;

    LOAD_KV(0, 0);

    for (int t = 0; t < ntiles; t++) {
        const int s  = t & 1;
        const int j0 = t * 64;
        asm volatile("cp.async.wait_group 0;\n" ::: "memory");
        __syncthreads();
        if (t + 1 < ntiles) LOAD_KV(s ^ 1, j0 + 64);

        const uint32_t kS = ks0 + s * ASTG;
        const uint32_t vS = vs0 + s * ASTG;

        float sv[8][4];
        #pragma unroll
        for (int nj = 0; nj < 8; nj++)
            #pragma unroll
            for (int f = 0; f < 4; f++) sv[nj][f] = 0.0f;
        #pragma unroll
        for (int kk = 0; kk < 4; kk++) {
            #pragma unroll
            for (int p = 0; p < 4; p++) {
                uint32_t bf[4];
                LDSM_X4(bf, kS + kOff + p * (16 * ASTR) + kk * 32);
                mma_f16(sv[2 * p],     qf[kk], bf[0], bf[1]);
                mma_f16(sv[2 * p + 1], qf[kk], bf[2], bf[3]);
            }
        }

        float mx0 = -1.0e30f, mx1 = -1.0e30f;
        #pragma unroll
        for (int nj = 0; nj < 8; nj++) {
            float2 bb = *(const float2*)&bg[j0 + nj * 8 + 2 * tig];
            sv[nj][0] = sv[nj][0] * SC2 + bb.x;
            sv[nj][1] = sv[nj][1] * SC2 + bb.y;
            sv[nj][2] = sv[nj][2] * SC2 + bb.x;
            sv[nj][3] = sv[nj][3] * SC2 + bb.y;
            mx0 = fmaxf(mx0, fmaxf(sv[nj][0], sv[nj][1]));
            mx1 = fmaxf(mx1, fmaxf(sv[nj][2], sv[nj][3]));
        }
        mx0 = fmaxf(mx0, __shfl_xor_sync(0xffffffffu, mx0, 1));
        mx0 = fmaxf(mx0, __shfl_xor_sync(0xffffffffu, mx0, 2));
        mx1 = fmaxf(mx1, __shfl_xor_sync(0xffffffffu, mx1, 1));
        mx1 = fmaxf(mx1, __shfl_xor_sync(0xffffffffu, mx1, 2));
        float mn0 = fmaxf(m0, mx0), mn1 = fmaxf(m1, mx1);
        float c0 = exp2f(m0 - mn0), c1 = exp2f(m1 - mn1);
        m0 = mn0; m1 = mn1;

        float sum0 = 0.0f, sum1 = 0.0f;
        #pragma unroll
        for (int nj = 0; nj < 8; nj++) {
            sv[nj][0] = exp2f(sv[nj][0] - m0);
            sv[nj][1] = exp2f(sv[nj][1] - m0);
            sv[nj][2] = exp2f(sv[nj][2] - m1);
            sv[nj][3] = exp2f(sv[nj][3] - m1);
            sum0 += sv[nj][0] + sv[nj][1];
            sum1 += sv[nj][2] + sv[nj][3];
        }
        sum0 += __shfl_xor_sync(0xffffffffu, sum0, 1);
        sum0 += __shfl_xor_sync(0xffffffffu, sum0, 2);
        sum1 += __shfl_xor_sync(0xffffffffu, sum1, 1);
        sum1 += __shfl_xor_sync(0xffffffffu, sum1, 2);
        l0 = l0 * c0 + sum0;
        l1 = l1 * c1 + sum1;

        #pragma unroll
        for (int nj = 0; nj < 8; nj++) {
            of[nj][0] *= c0; of[nj][1] *= c0;
            of[nj][2] *= c1; of[nj][3] *= c1;
        }

        #pragma unroll
        for (int kk2 = 0; kk2 < 4; kk2++) {
            uint32_t pf[4];
            pf[0] = ph2(sv[2 * kk2][0],     sv[2 * kk2][1]);
            pf[1] = ph2(sv[2 * kk2][2],     sv[2 * kk2][3]);
            pf[2] = ph2(sv[2 * kk2 + 1][0], sv[2 * kk2 + 1][1]);
            pf[3] = ph2(sv[2 * kk2 + 1][2], sv[2 * kk2 + 1][3]);
            #pragma unroll
            for (int p2 = 0; p2 < 4; p2++) {
                uint32_t bf[4];
                LDSM_X4_T(bf, vS + vOff + kk2 * (16 * ASTR) + p2 * 32);
                mma_f16(of[2 * p2],     pf, bf[0], bf[1]);
                mma_f16(of[2 * p2 + 1], pf, bf[2], bf[3]);
            }
        }
    }

    float inv0 = 1.0f / l0, inv1 = 1.0f / l1;
    #pragma unroll
    for (int nj = 0; nj < 8; nj++) {
        int col = nj * 8 + 2 * tig;
        __half* dst = &g_Oh[(size_t)(b * LQ + q0 + row0) * HID + h * DH + col];
        *(__half2*)dst = __floats2half2_rn(of[nj][0] * inv0, of[nj][1] * inv0);
        *(__half2*)(dst + (size_t)8 * HID) =
            __floats2half2_rn(of[nj][2] * inv1, of[nj][3] * inv1);
    }
}

// ---------------------------------------------------------------------------
// kernel_launch: two-stream fork/join (graph-capture-legal via events).
// Main stream: mask compaction -> gather -> Wk/Wv transpose -> KV GEMM.
// Side stream: Q to_half -> Wq transpose -> Q GEMM -> Wo transpose.
// Join before attention; O GEMM last.
// ---------------------------------------------------------------------------
extern "C" void kernel_launch(void* const* d_in, const int* in_sizes, int n_in,
                              void* d_out, int out_size) {
    (void)in_sizes; (void)n_in; (void)out_size;
    const float* query     = (const float*)d_in[0];
    const float* key_value = (const float*)d_in[1];
    const void*  mask      = d_in[2];
    const float* Wq = (const float*)d_in[3];
    const float* bq = (const float*)d_in[4];
    const float* Wk = (const float*)d_in[5];
    const float* bk = (const float*)d_in[6];
    const float* Wv = (const float*)d_in[7];
    const float* bv = (const float*)d_in[8];
    const float* Wo = (const float*)d_in[9];
    const float* bo = (const float*)d_in[10];
    float* out = (float*)d_out;

    __half *Qp, *KVp, *Qh, *KVh, *Oh, *WqT, *WkvT, *WoT;
    float  *bkv;
    int    *cpad;
    cudaGetSymbolAddress((void**)&Qp,   g_Qp);
    cudaGetSymbolAddress((void**)&KVp,  g_KVp);
    cudaGetSymbolAddress((void**)&Qh,   g_Qh);
    cudaGetSymbolAddress((void**)&KVh,  g_KVh);
    cudaGetSymbolAddress((void**)&Oh,   g_Oh);
    cudaGetSymbolAddress((void**)&WqT,  g_WqT);
    cudaGetSymbolAddress((void**)&WkvT, g_WkvT);
    cudaGetSymbolAddress((void**)&WoT,  g_WoT);
    cudaGetSymbolAddress((void**)&bkv,  g_bkv);
    cudaGetSymbolAddress((void**)&cpad, g_cpad);

    cudaStream_t s2;
    cudaStreamCreateWithFlags(&s2, cudaStreamNonBlocking);
    cudaEvent_t eF, eJ;
    cudaEventCreateWithFlags(&eF, cudaEventDisableTiming);
    cudaEventCreateWithFlags(&eJ, cudaEventDisableTiming);

    // fork side stream off the (captured) default stream
    cudaEventRecord(eF, 0);
    cudaStreamWaitEvent(s2, eF, 0);

    const int TPB = 256;
    dim3 tb(32, 8);

    // ---- side stream: Q chain + Wo transpose ----
    int n4 = (B_ * LQ * QDIM) / 4;
    to_half<<<(n4 + TPB - 1) / TPB, TPB, 0, s2>>>(query, Qh, n4);
    transpose_half<<<dim3(HID / 32, QDIM / 32), tb, 0, s2>>>(Wq, WqT, QDIM, HID);
    dim3 gq(HID / 128, (B_ * LQ) / 128, 1);
    gemm_f16<<<gq, 256, 0, s2>>>(Qh, WqT, bq, nullptr, Qp, HID, QDIM,
                                 nullptr, 0);
    transpose_half<<<dim3(HID / 32, HID / 32), tb, 0, s2>>>(Wo, WoT, HID, HID);

    // ---- main stream: mask compaction -> gather -> Wk/Wv -> KV GEMM ----
    compact_mask<<<B_, 256>>>(mask, bk, bv);
    int ng = B_ * LKV * (KVDIM / 8);
    gather_half<<<(ng + TPB - 1) / TPB, TPB>>>(key_value);
    transpose_half<<<dim3(HID / 32, KVDIM / 32), tb>>>(Wk, WkvT, KVDIM, HID);
    transpose_half<<<dim3(HID / 32, KVDIM / 32), tb>>>(
        Wv, WkvT + (size_t)HID * KVDIM, KVDIM, HID);
    dim3 gkv(KVW / 128, LKV / 128, B_);
    gemm_f16<<<gkv, 256>>>(KVh, WkvT, bkv, nullptr, KVp, KVW, KVDIM,
                           cpad, LKV);

    // join side stream, then attention + O projection on the main stream
    cudaEventRecord(eJ, s2);
    cudaStreamWaitEvent(0, eJ, 0);

    attn_f16<<<dim3(LQ / 128, B_ * NH), 256>>>();
    gemm_f16<<<gq, 256>>>(Oh, WoT, bo, out, nullptr, HID, HID, nullptr, 0);

    // cleanup only when not capturing (destroying forked handles mid-capture
    // is illegal); the rare capture call leaks one stream + two events.
    cudaStreamCaptureStatus st = cudaStreamCaptureStatusNone;
    cudaStreamIsCapturing(s2, &st);
    if (st == cudaStreamCaptureStatusNone) {
        cudaEventDestroy(eF);
        cudaEventDestroy(eJ);
        cudaStreamDestroy(s2);
    }
}

// round 17
// speedup vs baseline: 1.6691x; 1.0330x over previous
#include <cuda_runtime.h>
#include <cuda_fp16.h>
#include <math.h>
#include <stdint.h>

// Problem constants
#define B_    8
#define LQ    512
#define LKV   2048
#define QDIM  768
#define KVDIM 768
#define HID   1024
#define NH    16
#define DH    64
#define KVW   2048    // merged K|V projection row width

// ---------------------------------------------------------------------------
// Scratch (device globals)
// ---------------------------------------------------------------------------
__device__ __half g_Qp[(size_t)B_ * LQ * HID];     // projected Q (fp16)
__device__ __half g_KVp[(size_t)B_ * LKV * KVW];   // projected [K|V] (compact)
__device__ __half g_Oh[(size_t)B_ * LQ * HID];     // attention out (fp16)
__device__ float  g_cbias[B_ * LKV];               // compact bias (0 / -inf2)
__device__ float  g_bkv[KVW];                      // [bk|bv] concatenated
__device__ int    g_idx[B_ * LKV];                 // compact -> original kv idx
__device__ int    g_cnt[B_];                       // valid count per batch
__device__ int    g_jmax[B_];                      // ceil64(cnt)
__device__ int    g_cpad[B_];                      // ceil128(cnt)
// fp16 prep buffers
__device__ __half g_Qh[(size_t)B_ * LQ * QDIM];    // query fp16 [M][K]
__device__ __half g_KVh[(size_t)B_ * LKV * KVDIM]; // compacted key_value fp16
__device__ __half g_WqT[QDIM * HID];               // Wq^T fp16 [N][K]
__device__ __half g_WkvT[(size_t)KVW * KVDIM];     // [Wk^T | Wv^T] fp16
__device__ __half g_WoT[HID * HID];

// ---------------------------------------------------------------------------
// Helpers
// ---------------------------------------------------------------------------
__device__ __forceinline__ void mma_f16(float d[4], const uint32_t a[4],
                                        uint32_t b0, uint32_t b1) {
    asm volatile(
        "mma.sync.aligned.m16n8k16.row.col.f32.f16.f16.f32 "
        "{%0,%1,%2,%3}, {%4,%5,%6,%7}, {%8,%9}, {%0,%1,%2,%3};\n"
        : "+f"(d[0]), "+f"(d[1]), "+f"(d[2]), "+f"(d[3])
        : "r"(a[0]), "r"(a[1]), "r"(a[2]), "r"(a[3]), "r"(b0), "r"(b1));
}

#define LDSM_X4(r, addr)                                                      \
    asm volatile("ldmatrix.sync.aligned.m8n8.x4.shared.b16 {%0,%1,%2,%3}, [%4];" \
                 : "=r"((r)[0]), "=r"((r)[1]), "=r"((r)[2]), "=r"((r)[3])     \
                 : "r"(addr))

#define LDSM_X4_T(r, addr)                                                    \
    asm volatile("ldmatrix.sync.aligned.m8n8.x4.trans.shared.b16 {%0,%1,%2,%3}, [%4];" \
                 : "=r"((r)[0]), "=r"((r)[1]), "=r"((r)[2]), "=r"((r)[3])     \
                 : "r"(addr))

__device__ __forceinline__ void cp16(uint32_t dst_smem, const void* src) {
    asm volatile("cp.async.cg.shared.global [%0], [%1], 16;\n"
                 :: "r"(dst_smem), "l"(src));
}

__device__ __forceinline__ uint32_t smem_u32(const void* p) {
    uint32_t a;
    asm("{ .reg .u64 t; cvta.to.shared.u64 t, %1; cvt.u32.u64 %0, t; }"
        : "=r"(a) : "l"(p));
    return a;
}

__device__ __forceinline__ uint32_t ph2(float lo, float hi) {
    __half2 h = __floats2half2_rn(lo, hi);
    return *reinterpret_cast<uint32_t*>(&h);
}

// ---------------------------------------------------------------------------
// Prep kernels
// ---------------------------------------------------------------------------
__global__ void to_half(const float* __restrict__ s, __half* __restrict__ d,
                        int n4) {
    for (int i = blockIdx.x * blockDim.x + threadIdx.x; i < n4;
         i += gridDim.x * blockDim.x) {
        float4 v = ((const float4*)s)[i];
        ((__half2*)d)[i * 2]     = __floats2half2_rn(v.x, v.y);
        ((__half2*)d)[i * 2 + 1] = __floats2half2_rn(v.z, v.w);
    }
}

// W[K][N] fp32 -> WT[N][K] fp16. block (32,8), grid (N/32, K/32).
__global__ void transpose_half(const float* __restrict__ s,
                               __half* __restrict__ d, int K, int N) {
    __shared__ float t[32][33];
    int n0 = blockIdx.x * 32, k0 = blockIdx.y * 32;
    int tx = threadIdx.x, ty = threadIdx.y;
    #pragma unroll
    for (int i = 0; i < 32; i += 8)
        t[ty + i][tx] = s[(size_t)(k0 + ty + i) * N + n0 + tx];
    __syncthreads();
    #pragma unroll
    for (int i = 0; i < 32; i += 8)
        d[(size_t)(n0 + ty + i) * K + k0 + tx] = __float2half(t[tx][ty + i]);
}

// ---------------------------------------------------------------------------
// Mask compaction: one block (256 threads) per batch. Self-classifies the
// mask dtype, block-scans to deterministic ascending compact indices, writes
// cnt/jmax/cpad and the compact-domain pad bias. Block 0 also concats bk|bv.
// ---------------------------------------------------------------------------
__global__ void compact_mask(const void* __restrict__ mp,
                             const float* __restrict__ bk,
                             const float* __restrict__ bv) {
    __shared__ int wsum[8];
    __shared__ int s_total;
    __shared__ int sbad[2];
    const int b    = blockIdx.x;
    const int tid  = threadIdx.x;
    const int lane = tid & 31;
    const int wid  = tid >> 5;

    if (tid == 0) { sbad[0] = 0; sbad[1] = 0; }
    __syncthreads();
    {
        const unsigned int* wds = (const unsigned int*)mp;
        int lf = 0, li = 0;
        for (int i = tid; i < 1024; i += 256) {
            unsigned int x = wds[i];
            if (!(x == 0u || x == 0x3f800000u)) lf = 1;
            if (!(x == 0u || x == 1u))          li = 1;
        }
        if (lf) sbad[0] = 1;
        if (li) sbad[1] = 1;
    }
    __syncthreads();
    const int kind = (!sbad[0]) ? 0 : ((!sbad[1]) ? 1 : 2);

    const int base = b * LKV + tid * 8;
    bool v[8];
    int lc = 0;
    #pragma unroll
    for (int i = 0; i < 8; i++) {
        bool on;
        if (kind == 0)      on = (((const float*)mp)[base + i] != 0.0f);
        else if (kind == 1) on = (((const int*)mp)[base + i] != 0);
        else                on = (((const unsigned char*)mp)[base + i] != 0);
        v[i] = on;
        lc += on;
    }
    int pre = lc;
    #pragma unroll
    for (int d = 1; d < 32; d <<= 1) {
        int t = __shfl_up_sync(0xffffffffu, pre, d);
        if (lane >= d) pre += t;
    }
    int warp_total = __shfl_sync(0xffffffffu, pre, 31);
    int excl = pre - lc;
    if (lane == 31) wsum[wid] = warp_total;
    __syncthreads();
    if (wid == 0) {
        int wv = (lane < 8) ? wsum[lane] : 0;
        #pragma unroll
        for (int d = 1; d < 8; d <<= 1) {
            int t = __shfl_up_sync(0xffffffffu, wv, d);
            if (lane >= d) wv += t;
        }
        if (lane < 8) wsum[lane] = wv;
        if (lane == 7) s_total = wv;
    }
    __syncthreads();
    int off = excl + (wid > 0 ? wsum[wid - 1] : 0);
    #pragma unroll
    for (int i = 0; i < 8; i++)
        if (v[i]) g_idx[b * LKV + off++] = tid * 8 + i;

    const int total = s_total;
    if (tid == 0) {
        g_cnt[b]  = total;
        g_jmax[b] = (total + 63) & ~63;
        g_cpad[b] = (total + 127) & ~127;
    }
    for (int j = tid; j < LKV; j += 256)
        g_cbias[b * LKV + j] = (j < total) ? 0.0f : -1.4426950e30f;
    if (b == 0)
        for (int i = tid; i < HID; i += 256) {
            g_bkv[i] = bk[i];
            g_bkv[HID + i] = bv[i];
        }
}

// ---------------------------------------------------------------------------
// Gather + fp32->fp16 convert of valid kv rows into compact order.
// ---------------------------------------------------------------------------
__global__ void gather_half(const float* __restrict__ kv) {
    int t = blockIdx.x * blockDim.x + threadIdx.x;
    const int perrow = KVDIM / 8;                  // 96
    int b = t / (LKV * perrow);
    int rem = t % (LKV * perrow);
    int r = rem / perrow;
    int c = (rem % perrow) * 8;
    if (b >= B_) return;
    if (r >= g_cpad[b]) return;
    __half* dst = g_KVh + ((size_t)(b * LKV + r)) * KVDIM + c;
    if (r < g_cnt[b]) {
        const float* src = kv + ((size_t)(b * LKV + g_idx[b * LKV + r])) * KVDIM + c;
        float4 v0 = *(const float4*)(src);
        float4 v1 = *(const float4*)(src + 4);
        ((__half2*)dst)[0] = __floats2half2_rn(v0.x, v0.y);
        ((__half2*)dst)[1] = __floats2half2_rn(v0.z, v0.w);
        ((__half2*)dst)[2] = __floats2half2_rn(v1.x, v1.y);
        ((__half2*)dst)[3] = __floats2half2_rn(v1.z, v1.w);
    } else {
        ((__half2*)dst)[0] = __half2half2(__float2half(0.0f));
        ((__half2*)dst)[1] = __half2half2(__float2half(0.0f));
        ((__half2*)dst)[2] = __half2half2(__float2half(0.0f));
        ((__half2*)dst)[3] = __half2half2(__float2half(0.0f));
    }
}

// ---------------------------------------------------------------------------
// FP16 tensor-core GEMM (unchanged, hardware-validated).
// ---------------------------------------------------------------------------
#define GSTAGE 10240   // 128 rows * 80 B

#define LOAD_F16(st, k0)                                                      \
    do {                                                                      \
        _Pragma("unroll")                                                     \
        for (int i = 0; i < 2; i++) {                                         \
            int idx = tid + i * 256;                                          \
            int r = idx >> 2, c = idx & 3;                                    \
            cp16(saA + (st) * GSTAGE + r * 80 + c * 16,                       \
                 A + (size_t)(bym + r) * K + (k0) + c * 8);                   \
            cp16(saB + (st) * GSTAGE + r * 80 + c * 16,                       \
                 BT + (size_t)(bxn + r) * K + (k0) + c * 8);                  \
        }                                                                     \
        asm volatile("cp.async.commit_group;\n" ::: "memory");                \
    } while (0)

__global__ __launch_bounds__(256, 2) void gemm_f16(
    const __half* __restrict__ A, const __half* __restrict__ BT,
    const float* __restrict__ bias, float* __restrict__ Cf,
    __half* __restrict__ Ch, int N, int K,
    const int* __restrict__ dcnt, int bstride)
{
    const int bym = blockIdx.y * 128;
    if (dcnt && bym >= dcnt[blockIdx.z]) return;

    __shared__ __align__(16) __half As[2][128][40];
    __shared__ __align__(16) __half Bs[2][128][40];

    const size_t boff = (size_t)blockIdx.z * bstride;
    A  += boff * K;
    if (Cf) Cf += boff * N;
    if (Ch) Ch += boff * N;

    const int tid  = threadIdx.x;
    const int lane = tid & 31;
    const int wid  = tid >> 5;
    const int g    = lane >> 2;
    const int tig  = lane & 3;
    const int wm   = (wid >> 2) * 64;
    const int wn   = (wid & 3) * 32;
    const int bxn  = blockIdx.x * 128;

    const uint32_t saA = smem_u32(&As[0][0][0]);
    const uint32_t saB = smem_u32(&Bs[0][0][0]);

    const int lr  = lane & 7;
    const int seg = lane >> 3;
    const uint32_t aOff = (uint32_t)(wm + lr + (seg & 1) * 8) * 80
                        + ((seg >> 1) & 1) * 16;
    const uint32_t bOff = (uint32_t)(wn + lr + ((seg >> 1) & 1) * 8) * 80
                        + (seg & 1) * 16;

    float acc[4][4][4];
    #pragma unroll
    for (int mi = 0; mi < 4; mi++)
        #pragma unroll
        for (int nj = 0; nj < 4; nj++)
            #pragma unroll
            for (int f = 0; f < 4; f++) acc[mi][nj][f] = 0.0f;

    const int T = K >> 5;
    LOAD_F16(0, 0);

    for (int t = 0; t < T; t++) {
        const int s = t & 1;
        asm volatile("cp.async.wait_group 0;\n" ::: "memory");
        __syncthreads();
        if (t + 1 < T) LOAD_F16(s ^ 1, (t + 1) << 5);

        const uint32_t aS = saA + s * GSTAGE + aOff;
        const uint32_t bS = saB + s * GSTAGE + bOff;
        #pragma unroll
        for (int ks = 0; ks < 2; ks++) {
            const uint32_t kb = ks * 32;
            uint32_t af[4][4], bf[2][4];
            #pragma unroll
            for (int mi = 0; mi < 4; mi++)
                LDSM_X4(af[mi], aS + mi * (16 * 80) + kb);
            #pragma unroll
            for (int p = 0; p < 2; p++)
                LDSM_X4(bf[p], bS + p * (16 * 80) + kb);
            #pragma unroll
            for (int mi = 0; mi < 4; mi++)
                #pragma unroll
                for (int nj = 0; nj < 4; nj++)
                    mma_f16(acc[mi][nj], af[mi],
                            bf[nj >> 1][(nj & 1) * 2],
                            bf[nj >> 1][(nj & 1) * 2 + 1]);
        }
    }

    #pragma unroll
    for (int mi = 0; mi < 4; mi++) {
        int row = bym + wm + mi * 16 + g;
        #pragma unroll
        for (int nj = 0; nj < 4; nj++) {
            int col = bxn + wn + nj * 8 + 2 * tig;
            float b0 = bias[col], b1 = bias[col + 1];
            float v00 = acc[mi][nj][0] + b0, v01 = acc[mi][nj][1] + b1;
            float v10 = acc[mi][nj][2] + b0, v11 = acc[mi][nj][3] + b1;
            if (Ch) {
                *(__half2*)&Ch[(size_t)row * N + col] =
                    __floats2half2_rn(v00, v01);
                *(__half2*)&Ch[(size_t)(row + 8) * N + col] =
                    __floats2half2_rn(v10, v11);
            } else {
                *(float2*)&Cf[(size_t)row * N + col] = make_float2(v00, v01);
                *(float2*)&Cf[(size_t)(row + 8) * N + col] =
                    make_float2(v10, v11);
            }
        }
    }
}

// ---------------------------------------------------------------------------
// Fused flash attention over the COMPACT kv sequence (unchanged).
// ---------------------------------------------------------------------------
#define ASTR 144
#define ASTG (64 * ASTR)
#define SC2  0.18033688f      // 0.125 * log2(e)

#define LOAD_KV(st, j0)                                                       \
    do {                                                                      \
        _Pragma("unroll")                                                     \
        for (int i = 0; i < 2; i++) {                                         \
            int idx = tid + i * 256;                                          \
            int r = idx >> 3, c = idx & 7;                                    \
            cp16(ks0 + (st) * ASTG + r * ASTR + c * 16,                       \
                 Kg + (size_t)((j0) + r) * KVW + c * 8);                      \
            cp16(vs0 + (st) * ASTG + r * ASTR + c * 16,                       \
                 Vg + (size_t)((j0) + r) * KVW + c * 8);                      \
        }                                                                     \
        asm volatile("cp.async.commit_group;\n" ::: "memory");                \
    } while (0)

__global__ __launch_bounds__(256) void attn_f16() {
    __shared__ __align__(16) __half Ks[2][64][ASTR / 2];
    __shared__ __align__(16) __half Vs[2][64][ASTR / 2];

    const int tid  = threadIdx.x;
    const int lane = tid & 31;
    const int w    = tid >> 5;
    const int g    = lane >> 2;
    const int tig  = lane & 3;
    const int lr   = lane & 7;
    const int seg  = lane >> 3;
    const int bh   = blockIdx.y;
    const int b    = bh >> 4;
    const int h    = bh & 15;
    const int q0   = blockIdx.x * 128;
    const int row0 = w * 16 + g;

    const __half* Qg = g_Qp + ((size_t)(b * LQ + q0)) * HID + h * DH;
    const __half* Kg = g_KVp + ((size_t)b * LKV) * KVW + h * DH;
    const __half* Vg = Kg + HID;
    const float*  bg = g_cbias + b * LKV;
    const int     ntiles = g_jmax[b] >> 6;

    const uint32_t ks0 = smem_u32(&Ks[0][0][0]);
    const uint32_t vs0 = smem_u32(&Vs[0][0][0]);

    const uint32_t kOff = (uint32_t)(lr + ((seg >> 1) & 1) * 8) * ASTR
                        + (seg & 1) * 16;
    const uint32_t vOff = (uint32_t)(lr + (seg & 1) * 8) * ASTR
                        + ((seg >> 1) & 1) * 16;

    uint32_t qf[4][4];
    {
        const __half* q0p = Qg + (size_t)row0 * HID;
        const __half* q8p = Qg + (size_t)(row0 + 8) * HID;
        #pragma unroll
        for (int kk = 0; kk < 4; kk++) {
            int col = kk * 16 + 2 * tig;
            qf[kk][0] = *(const uint32_t*)(q0p + col);
            qf[kk][1] = *(const uint32_t*)(q8p + col);
            qf[kk][2] = *(const uint32_t*)(q0p + col + 8);
            qf[kk][3] = *(const uint32_t*)(q8p + col + 8);
        }
    }

    float of[8][4];
    #pragma unroll
    for (int nj = 0; nj < 8; nj++)
        #pragma unroll
        for (int f = 0; f < 4; f++) of[nj][f] = 0.0f;
    float m0 = -1.0e30f, m1 = -1.0e30f, l0 = 0.0f, l1 = 0.0f;

    LOAD_KV(0, 0);

    for (int t = 0; t < ntiles; t++) {
        const int s  = t & 1;
        const int j0 = t * 64;
        asm volatile("cp.async.wait_group 0;\n" ::: "memory");
        __syncthreads();
        if (t + 1 < ntiles) LOAD_KV(s ^ 1, j0 + 64);

        const uint32_t kS = ks0 + s * ASTG;
        const uint32_t vS = vs0 + s * ASTG;

        float sv[8][4];
        #pragma unroll
        for (int nj = 0; nj < 8; nj++)
            #pragma unroll
            for (int f = 0; f < 4; f++) sv[nj][f] = 0.0f;
        #pragma unroll
        for (int kk = 0; kk < 4; kk++) {
            #pragma unroll
            for (int p = 0; p < 4; p++) {
                uint32_t bf[4];
                LDSM_X4(bf, kS + kOff + p * (16 * ASTR) + kk * 32);
                mma_f16(sv[2 * p],     qf[kk], bf[0], bf[1]);
                mma_f16(sv[2 * p + 1], qf[kk], bf[2], bf[3]);
            }
        }

        float mx0 = -1.0e30f, mx1 = -1.0e30f;
        #pragma unroll
        for (int nj = 0; nj < 8; nj++) {
            float2 bb = *(const float2*)&bg[j0 + nj * 8 + 2 * tig];
            sv[nj][0] = sv[nj][0] * SC2 + bb.x;
            sv[nj][1] = sv[nj][1] * SC2 + bb.y;
            sv[nj][2] = sv[nj][2] * SC2 + bb.x;
            sv[nj][3] = sv[nj][3] * SC2 + bb.y;
            mx0 = fmaxf(mx0, fmaxf(sv[nj][0], sv[nj][1]));
            mx1 = fmaxf(mx1, fmaxf(sv[nj][2], sv[nj][3]));
        }
        mx0 = fmaxf(mx0, __shfl_xor_sync(0xffffffffu, mx0, 1));
        mx0 = fmaxf(mx0, __shfl_xor_sync(0xffffffffu, mx0, 2));
        mx1 = fmaxf(mx1, __shfl_xor_sync(0xffffffffu, mx1, 1));
        mx1 = fmaxf(mx1, __shfl_xor_sync(0xffffffffu, mx1, 2));
        float mn0 = fmaxf(m0, mx0), mn1 = fmaxf(m1, mx1);
        float c0 = exp2f(m0 - mn0), c1 = exp2f(m1 - mn1);
        m0 = mn0; m1 = mn1;

        float sum0 = 0.0f, sum1 = 0.0f;
        #pragma unroll
        for (int nj = 0; nj < 8; nj++) {
            sv[nj][0] = exp2f(sv[nj][0] - m0);
            sv[nj][1] = exp2f(sv[nj][1] - m0);
            sv[nj][2] = exp2f(sv[nj][2] - m1);
            sv[nj][3] = exp2f(sv[nj][3] - m1);
            sum0 += sv[nj][0] + sv[nj][1];
            sum1 += sv[nj][2] + sv[nj][3];
        }
        sum0 += __shfl_xor_sync(0xffffffffu, sum0, 1);
        sum0 += __shfl_xor_sync(0xffffffffu, sum0, 2);
        sum1 += __shfl_xor_sync(0xffffffffu, sum1, 1);
        sum1 += __shfl_xor_sync(0xffffffffu, sum1, 2);
        l0 = l0 * c0 + sum0;
        l1 = l1 * c1 + sum1;

        #pragma unroll
        for (int nj = 0; nj < 8; nj++) {
            of[nj][0] *= c0; of[nj][1] *= c0;
            of[nj][2] *= c1; of[nj][3] *= c1;
        }

        #pragma unroll
        for (int kk2 = 0; kk2 < 4; kk2++) {
            uint32_t pf[4];
            pf[0] = ph2(sv[2 * kk2][0],     sv[2 * kk2][1]);
            pf[1] = ph2(sv[2 * kk2][2],     sv[2 * kk2][3]);
            pf[2] = ph2(sv[2 * kk2 + 1][0], sv[2 * kk2 + 1][1]);
            pf[3] = ph2(sv[2 * kk2 + 1][2], sv[2 * kk2 + 1][3]);
            #pragma unroll
            for (int p2 = 0; p2 < 4; p2++) {
                uint32_t bf[4];
                LDSM_X4_T(bf, vS + vOff + kk2 * (16 * ASTR) + p2 * 32);
                mma_f16(of[2 * p2],     pf, bf[0], bf[1]);
                mma_f16(of[2 * p2 + 1], pf, bf[2], bf[3]);
            }
        }
    }

    float inv0 = 1.0f / l0, inv1 = 1.0f / l1;
    #pragma unroll
    for (int nj = 0; nj < 8; nj++) {
        int col = nj * 8 + 2 * tig;
        __half* dst = &g_Oh[(size_t)(b * LQ + q0 + row0) * HID + h * DH + col];
        *(__half2*)dst = __floats2half2_rn(of[nj][0] * inv0, of[nj][1] * inv0);
        *(__half2*)(dst + (size_t)8 * HID) =
            __floats2half2_rn(of[nj][2] * inv1, of[nj][3] * inv1);
    }
}

// ---------------------------------------------------------------------------
// kernel_launch: two-stream fork with fine-grained event joins.
// Side stream: WkT -> WvT -> [eKV] -> Qh -> WqT -> Q GEMM -> [eQ] -> WoT -> [eO]
// Main stream: compact -> gather -> wait(eKV) -> KV GEMM -> wait(eQ) -> attn
//              -> wait(eO) -> O GEMM.
// ---------------------------------------------------------------------------
extern "C" void kernel_launch(void* const* d_in, const int* in_sizes, int n_in,
                              void* d_out, int out_size) {
    (void)in_sizes; (void)n_in; (void)out_size;
    const float* query     = (const float*)d_in[0];
    const float* key_value = (const float*)d_in[1];
    const void*  mask      = d_in[2];
    const float* Wq = (const float*)d_in[3];
    const float* bq = (const float*)d_in[4];
    const float* Wk = (const float*)d_in[5];
    const float* bk = (const float*)d_in[6];
    const float* Wv = (const float*)d_in[7];
    const float* bv = (const float*)d_in[8];
    const float* Wo = (const float*)d_in[9];
    const float* bo = (const float*)d_in[10];
    float* out = (float*)d_out;

    __half *Qp, *KVp, *Qh, *KVh, *Oh, *WqT, *WkvT, *WoT;
    float  *bkv;
    int    *cpad;
    cudaGetSymbolAddress((void**)&Qp,   g_Qp);
    cudaGetSymbolAddress((void**)&KVp,  g_KVp);
    cudaGetSymbolAddress((void**)&Qh,   g_Qh);
    cudaGetSymbolAddress((void**)&KVh,  g_KVh);
    cudaGetSymbolAddress((void**)&Oh,   g_Oh);
    cudaGetSymbolAddress((void**)&WqT,  g_WqT);
    cudaGetSymbolAddress((void**)&WkvT, g_WkvT);
    cudaGetSymbolAddress((void**)&WoT,  g_WoT);
    cudaGetSymbolAddress((void**)&bkv,  g_bkv);
    cudaGetSymbolAddress((void**)&cpad, g_cpad);

    cudaStream_t s2;
    cudaStreamCreateWithFlags(&s2, cudaStreamNonBlocking);
    cudaEvent_t eF, eKV, eQ, eO;
    cudaEventCreateWithFlags(&eF,  cudaEventDisableTiming);
    cudaEventCreateWithFlags(&eKV, cudaEventDisableTiming);
    cudaEventCreateWithFlags(&eQ,  cudaEventDisableTiming);
    cudaEventCreateWithFlags(&eO,  cudaEventDisableTiming);

    // fork side stream off the (captured) default stream
    cudaEventRecord(eF, 0);
    cudaStreamWaitEvent(s2, eF, 0);

    const int TPB = 256;
    dim3 tb(32, 8);
    dim3 gq(HID / 128, (B_ * LQ) / 128, 1);

    // ---- side stream ----
    transpose_half<<<dim3(HID / 32, KVDIM / 32), tb, 0, s2>>>(
        Wk, WkvT, KVDIM, HID);
    transpose_half<<<dim3(HID / 32, KVDIM / 32), tb, 0, s2>>>(
        Wv, WkvT + (size_t)HID * KVDIM, KVDIM, HID);
    cudaEventRecord(eKV, s2);
    int n4 = (B_ * LQ * QDIM) / 4;
    to_half<<<(n4 + TPB - 1) / TPB, TPB, 0, s2>>>(query, Qh, n4);
    transpose_half<<<dim3(HID / 32, QDIM / 32), tb, 0, s2>>>(Wq, WqT, QDIM, HID);
    gemm_f16<<<gq, 256, 0, s2>>>(Qh, WqT, bq, nullptr, Qp, HID, QDIM,
                                 nullptr, 0);
    cudaEventRecord(eQ, s2);
    transpose_half<<<dim3(HID / 32, HID / 32), tb, 0, s2>>>(Wo, WoT, HID, HID);
    cudaEventRecord(eO, s2);

    // ---- main stream ----
    compact_mask<<<B_, 256>>>(mask, bk, bv);
    int ng = B_ * LKV * (KVDIM / 8);
    gather_half<<<(ng + TPB - 1) / TPB, TPB>>>(key_value);
    cudaStreamWaitEvent(0, eKV, 0);
    dim3 gkv(KVW / 128, LKV / 128, B_);
    gemm_f16<<<gkv, 256>>>(KVh, WkvT, bkv, nullptr, KVp, KVW, KVDIM,
                           cpad, LKV);
    cudaStreamWaitEvent(0, eQ, 0);
    attn_f16<<<dim3(LQ / 128, B_ * NH), 256>>>();
    cudaStreamWaitEvent(0, eO, 0);
    gemm_f16<<<gq, 256>>>(Oh, WoT, bo, out, nullptr, HID, HID, nullptr, 0);

    // cleanup only when not capturing
    cudaStreamCaptureStatus st = cudaStreamCaptureStatusNone;
    cudaStreamIsCapturing(s2, &st);
    if (st == cudaStreamCaptureStatusNone) {
        cudaEventDestroy(eF);
        cudaEventDestroy(eKV);
        cudaEventDestroy(eQ);
        cudaEventDestroy(eO);
        cudaStreamDestroy(s2);
    }
}